// round 8
// baseline (speedup 1.0000x reference)
#include <cuda_runtime.h>
#include <cuda_bf16.h>
#include <math.h>
#include <stdint.h>

#define N_USERS 100000
#define N_ITEMS 50000
#define N_TOT   150000
#define IN_DIM  768
#define BR      64
#define NE      2097152
#define BATCHB  4096
#define NCAND   128
#define NNEG    16
#define DIM     128
#define INV_SQRT2 0.70710678118f
#define NB_SCAN 147
#define UMARK_WORDS ((N_USERS + 31) / 32)

// ---------------- scratch (device globals; NEVER referenced from host code) ----------------
__device__ float g_l1   [(size_t)N_TOT * BR];
__device__ float g_l2   [(size_t)N_TOT * BR];
__device__ float g_acc  [(size_t)N_TOT * BR];   // only marked-user rows written (layer 3)
__device__ float g_i_all[(size_t)N_ITEMS * DIM];
__device__ float g_batch_u[(size_t)BATCHB * DIM];
__device__ int   g_row_ptr[N_TOT + 1];
__device__ int   g_row_cnt[N_TOT];
__device__ int   g_row_fill[N_TOT];
__device__ int2  g_cv[NE];
__device__ int   g_bsum[256];
__device__ unsigned g_umark[UMARK_WORDS];
__device__ float g_loss;

// ---------------- zero counters / marks ----------------
__global__ void k_zero() {
    int i = blockIdx.x * blockDim.x + threadIdx.x;
    if (i < N_TOT) { g_row_cnt[i] = 0; g_row_fill[i] = 0; }
    if (i < UMARK_WORDS) g_umark[i] = 0u;
    if (i == 0) g_loss = 0.0f;
}

__global__ void k_mark(const int* __restrict__ uids) {
    int i = blockIdx.x * blockDim.x + threadIdx.x;
    if (i < BATCHB) {
        int u = uids[i];
        atomicOr(&g_umark[u >> 5], 1u << (u & 31));
    }
}

// ---------------- CSR build ----------------
__global__ void k_hist(const int* __restrict__ rows) {
    int i = blockIdx.x * blockDim.x + threadIdx.x;
    if (i < NE) atomicAdd(&g_row_cnt[rows[i]], 1);
}

__global__ void k_scan1() {
    __shared__ int red[256];
    int b = blockIdx.x, t = threadIdx.x;
    int base = b * 1024 + t * 4;
    int s = 0;
    #pragma unroll
    for (int q = 0; q < 4; q++) { int i = base + q; if (i < N_TOT) s += g_row_cnt[i]; }
    red[t] = s; __syncthreads();
    for (int off = 128; off > 0; off >>= 1) {
        if (t < off) red[t] += red[t + off];
        __syncthreads();
    }
    if (t == 0) g_bsum[b] = red[0];
}

__global__ void k_scan2() {
    if (threadIdx.x == 0 && blockIdx.x == 0) {
        int run = 0;
        for (int i = 0; i < NB_SCAN; i++) { int t = g_bsum[i]; g_bsum[i] = run; run += t; }
    }
}

__global__ void k_scan3() {
    __shared__ int tsum[256];
    int b = blockIdx.x, t = threadIdx.x;
    int base = b * 1024 + t * 4;
    int c0 = 0, c1 = 0, c2 = 0, c3 = 0;
    if (base + 0 < N_TOT) c0 = g_row_cnt[base + 0];
    if (base + 1 < N_TOT) c1 = g_row_cnt[base + 1];
    if (base + 2 < N_TOT) c2 = g_row_cnt[base + 2];
    if (base + 3 < N_TOT) c3 = g_row_cnt[base + 3];
    int p1 = c0, p2 = c0 + c1, p3 = c0 + c1 + c2, s = p3 + c3;
    tsum[t] = s; __syncthreads();
    for (int off = 1; off < 256; off <<= 1) {
        int v = (t >= off) ? tsum[t - off] : 0;
        __syncthreads();
        tsum[t] += v;
        __syncthreads();
    }
    int excl = tsum[t] - s + g_bsum[b];
    if (base + 0 < N_TOT) g_row_ptr[base + 0] = excl;
    if (base + 1 < N_TOT) g_row_ptr[base + 1] = excl + p1;
    if (base + 2 < N_TOT) g_row_ptr[base + 2] = excl + p2;
    if (base + 3 < N_TOT) g_row_ptr[base + 3] = excl + p3;
    if (b == 0 && t == 0) g_row_ptr[N_TOT] = NE;
}

__global__ void k_scatter(const int* __restrict__ rows, const int* __restrict__ cols,
                          const float* __restrict__ vals) {
    int i = blockIdx.x * blockDim.x + threadIdx.x;
    if (i >= NE) return;
    int r = rows[i];
    int ofs = atomicAdd(&g_row_fill[r], 1);
    g_cv[g_row_ptr[r] + ofs] = make_int2(cols[i], __float_as_int(vals[i]));
}

// ---------------- SpMM: HALF-WARP per destination row, float4 gathers ----------------
// MODE 0: gather raw(uw/iw) -> g_l1
// MODE 1: gather g_l1       -> g_l2
// MODE 2: gather g_l2; epilogue acc = raw + l1 + l2 + l3; items -> g_i_all (normalized),
//         marked users -> g_acc. Unmarked users skipped (len=0 but still shfl-participating).
template<int MODE>
__global__ void k_spmm(const float* __restrict__ uw, const float* __restrict__ iw) {
    int tid = blockIdx.x * blockDim.x + threadIdx.x;
    int w = tid >> 4;                 // half-warp id = destination row
    int l = threadIdx.x & 15;         // lane within half
    int half16 = threadIdx.x & 16;    // 0 for lower half, 16 for upper

    bool valid = (w < N_TOT);
    if (MODE == 2 && valid && w < N_USERS && !((g_umark[w >> 5] >> (w & 31)) & 1u))
        valid = false;

    int s = 0, e = 0;
    if (valid) { s = g_row_ptr[w]; e = g_row_ptr[w + 1]; }
    int len = e - s;
    int olen = __shfl_xor_sync(0xffffffffu, len, 16);
    int maxlen = max(len, olen);

    float a0 = 0.0f, a1 = 0.0f, a2 = 0.0f, a3 = 0.0f;

    for (int base = 0; base < maxlen; base += 16) {
        int idx = s + base + l;
        int c = 0; float v = 0.0f;
        if (idx < e) { int2 cv = __ldg(&g_cv[idx]); c = cv.x; v = __int_as_float(cv.y); }
        int cnt = len - base; cnt = min(16, max(cnt, 0));
        int ocnt = __shfl_xor_sync(0xffffffffu, cnt, 16);
        int m4 = (max(cnt, ocnt) + 3) & ~3;
        for (int j = 0; j < m4; j += 4) {
            int cc0 = __shfl_sync(0xffffffffu, c, half16 + j);
            int cc1 = __shfl_sync(0xffffffffu, c, half16 + j + 1);
            int cc2 = __shfl_sync(0xffffffffu, c, half16 + j + 2);
            int cc3 = __shfl_sync(0xffffffffu, c, half16 + j + 3);
            float vv0 = __shfl_sync(0xffffffffu, v, half16 + j);
            float vv1 = __shfl_sync(0xffffffffu, v, half16 + j + 1);
            float vv2 = __shfl_sync(0xffffffffu, v, half16 + j + 2);
            float vv3 = __shfl_sync(0xffffffffu, v, half16 + j + 3);
            const float *b0, *b1, *b2, *b3;
            if (MODE == 0) {
                b0 = (cc0 < N_USERS) ? uw + (size_t)cc0 * BR : iw + (size_t)(cc0 - N_USERS) * BR;
                b1 = (cc1 < N_USERS) ? uw + (size_t)cc1 * BR : iw + (size_t)(cc1 - N_USERS) * BR;
                b2 = (cc2 < N_USERS) ? uw + (size_t)cc2 * BR : iw + (size_t)(cc2 - N_USERS) * BR;
                b3 = (cc3 < N_USERS) ? uw + (size_t)cc3 * BR : iw + (size_t)(cc3 - N_USERS) * BR;
            } else {
                const float* in = (MODE == 1) ? g_l1 : g_l2;
                b0 = in + (size_t)cc0 * BR;
                b1 = in + (size_t)cc1 * BR;
                b2 = in + (size_t)cc2 * BR;
                b3 = in + (size_t)cc3 * BR;
            }
            float4 p0 = __ldg((const float4*)b0 + l);
            float4 p1 = __ldg((const float4*)b1 + l);
            float4 p2 = __ldg((const float4*)b2 + l);
            float4 p3 = __ldg((const float4*)b3 + l);
            a0 = fmaf(vv0, p0.x, a0); a1 = fmaf(vv0, p0.y, a1);
            a2 = fmaf(vv0, p0.z, a2); a3 = fmaf(vv0, p0.w, a3);
            a0 = fmaf(vv1, p1.x, a0); a1 = fmaf(vv1, p1.y, a1);
            a2 = fmaf(vv1, p1.z, a2); a3 = fmaf(vv1, p1.w, a3);
            a0 = fmaf(vv2, p2.x, a0); a1 = fmaf(vv2, p2.y, a1);
            a2 = fmaf(vv2, p2.z, a2); a3 = fmaf(vv2, p2.w, a3);
            a0 = fmaf(vv3, p3.x, a0); a1 = fmaf(vv3, p3.y, a1);
            a2 = fmaf(vv3, p3.z, a2); a3 = fmaf(vv3, p3.w, a3);
        }
    }

    if (MODE == 2) {
        // epilogue needs width-16 reductions: keep all lanes participating
        float t0 = 0, t1 = 0, t2 = 0, t3 = 0;
        if (valid) {
            const float* rp = (w < N_USERS) ? uw + (size_t)w * BR
                                            : iw + (size_t)(w - N_USERS) * BR;
            float4 r  = __ldg((const float4*)rp + l);
            float4 x1 = *((const float4*)(g_l1 + (size_t)w * BR) + l);
            float4 x2 = *((const float4*)(g_l2 + (size_t)w * BR) + l);
            t0 = r.x + x1.x + x2.x + a0;
            t1 = r.y + x1.y + x2.y + a1;
            t2 = r.z + x1.z + x2.z + a2;
            t3 = r.w + x1.w + x2.w + a3;
        }
        float ss = t0 * t0 + t1 * t1 + t2 * t2 + t3 * t3;
        #pragma unroll
        for (int off = 8; off > 0; off >>= 1)
            ss += __shfl_xor_sync(0xffffffffu, ss, off);   // stays within the 16-lane half
        if (valid) {
            if (w < N_USERS) {
                *((float4*)(g_acc + (size_t)w * BR) + l) = make_float4(t0, t1, t2, t3);
            } else {
                float sc = INV_SQRT2 / fmaxf(sqrtf(ss), 1e-12f);
                float* op = g_i_all + (size_t)(w - N_USERS) * DIM;
                *((float4*)op + l) = make_float4(t0 * sc, t1 * sc, t2 * sc, t3 * sc);
            }
        }
    } else if (valid) {
        float* op = (MODE == 0) ? g_l1 : g_l2;
        *((float4*)(op + (size_t)w * BR) + l) = make_float4(a0, a1, a2, a3);
    }
}

__global__ void k_collab_users(const int* __restrict__ uids) {
    int w = (blockIdx.x * blockDim.x + threadIdx.x) >> 5;
    int lane = threadIdx.x & 31;
    if (w >= BATCHB) return;
    int u = uids[w];
    size_t o = (size_t)u * BR;
    float v0 = g_acc[o + lane], v1 = g_acc[o + lane + 32];
    float ss = v0 * v0 + v1 * v1;
    #pragma unroll
    for (int off = 16; off > 0; off >>= 1) ss += __shfl_xor_sync(0xffffffffu, ss, off);
    float sc = INV_SQRT2 / fmaxf(sqrtf(ss), 1e-12f);
    g_batch_u[(size_t)w * DIM + lane] = v0 * sc;
    g_batch_u[(size_t)w * DIM + lane + 32] = v1 * sc;
}

// ---------------- split-bf16 mma.sync semantic GEMM ----------------
#define KC 64
#define KP 72
#define NCHUNKS (IN_DIM / KC)
#define SA_H 0
#define SA_L (128 * KP)
#define SB_H (2 * 128 * KP)
#define SB_L (2 * 128 * KP + 64 * KP)
#define SM_U16_TOTAL (2 * 128 * KP + 2 * 64 * KP)
#define SM_BYTES (SM_U16_TOTAL * 2)

__device__ __forceinline__ void mma_bf16(float* d, uint32_t a0, uint32_t a1, uint32_t a2,
                                         uint32_t a3, uint32_t b0, uint32_t b1) {
    asm volatile("mma.sync.aligned.m16n8k16.row.col.f32.bf16.bf16.f32 "
                 "{%0,%1,%2,%3}, {%4,%5,%6,%7}, {%8,%9}, {%0,%1,%2,%3};"
                 : "+f"(d[0]), "+f"(d[1]), "+f"(d[2]), "+f"(d[3])
                 : "r"(a0), "r"(a1), "r"(a2), "r"(a3), "r"(b0), "r"(b1));
}

__device__ __forceinline__ void split2(float x, float y, uint32_t& hi, uint32_t& lo) {
    uint32_t xi = __float_as_uint(x), yi = __float_as_uint(y);
    hi = __byte_perm(xi, yi, 0x7632);
    float lx = x - __uint_as_float(xi & 0xFFFF0000u);
    float ly = y - __uint_as_float(yi & 0xFFFF0000u);
    __nv_bfloat162 p = __floats2bfloat162_rn(lx, ly);
    lo = *(uint32_t*)&p;
}

template<bool GATHER>
__global__ void __launch_bounds__(256) k_sem_mma(const float* __restrict__ A,
                                                 const float* __restrict__ W,
                                                 const float* __restrict__ bias,
                                                 const int* __restrict__ gidx, int M) {
    extern __shared__ uint16_t sm[];
    float* __restrict__ outp = GATHER ? g_batch_u : g_i_all;
    int t = threadIdx.x, wid = t >> 5, lane = t & 31;
    int rowbase = blockIdx.x * 128;

    int ar = t >> 1, kh = (t & 1) * 32;
    int gr = rowbase + ar;
    bool av = gr < M;
    int srow = av ? (GATHER ? __ldg(gidx + gr) : gr) : 0;
    const float* arp = A + (size_t)srow * IN_DIM;

    int bn = t & 63, bk0 = t >> 6;

    float acc[8][4];
    #pragma unroll
    for (int i = 0; i < 8; i++)
        #pragma unroll
        for (int j = 0; j < 4; j++) acc[i][j] = 0.0f;

    int mr = wid * 16;
    int r0 = mr + (lane >> 2);
    int kq0 = (lane & 3) * 2;

    for (int ch = 0; ch < NCHUNKS; ch++) {
        int k0 = ch * KC;
        __syncthreads();
        #pragma unroll
        for (int i = 0; i < 8; i++) {
            int k = kh + i * 4;
            float4 a = av ? __ldg((const float4*)(arp + k0 + k)) : make_float4(0, 0, 0, 0);
            uint32_t h01, l01, h23, l23;
            split2(a.x, a.y, h01, l01);
            split2(a.z, a.w, h23, l23);
            int o = ar * KP + k;
            *(uint32_t*)(sm + SA_H + o)     = h01;
            *(uint32_t*)(sm + SA_H + o + 2) = h23;
            *(uint32_t*)(sm + SA_L + o)     = l01;
            *(uint32_t*)(sm + SA_L + o + 2) = l23;
        }
        #pragma unroll
        for (int i = 0; i < 16; i++) {
            int k = bk0 + i * 4;
            float wv = __ldg(W + (size_t)(k0 + k) * BR + bn);
            uint32_t wi = __float_as_uint(wv);
            float lo = wv - __uint_as_float(wi & 0xFFFF0000u);
            __nv_bfloat16 bl = __float2bfloat16(lo);
            int o = bn * KP + k;
            sm[SB_H + o] = (uint16_t)(wi >> 16);
            sm[SB_L + o] = *(uint16_t*)&bl;
        }
        __syncthreads();
        #pragma unroll
        for (int ks = 0; ks < 4; ks++) {
            int kq = ks * 16 + kq0;
            const uint16_t* pah = sm + SA_H + kq;
            const uint16_t* pal = sm + SA_L + kq;
            uint32_t ah0 = *(const uint32_t*)(pah + r0 * KP);
            uint32_t ah1 = *(const uint32_t*)(pah + (r0 + 8) * KP);
            uint32_t ah2 = *(const uint32_t*)(pah + r0 * KP + 8);
            uint32_t ah3 = *(const uint32_t*)(pah + (r0 + 8) * KP + 8);
            uint32_t al0 = *(const uint32_t*)(pal + r0 * KP);
            uint32_t al1 = *(const uint32_t*)(pal + (r0 + 8) * KP);
            uint32_t al2 = *(const uint32_t*)(pal + r0 * KP + 8);
            uint32_t al3 = *(const uint32_t*)(pal + (r0 + 8) * KP + 8);
            #pragma unroll
            for (int nt = 0; nt < 8; nt++) {
                int n = nt * 8 + (lane >> 2);
                uint32_t bh0 = *(const uint32_t*)(sm + SB_H + n * KP + kq);
                uint32_t bh1 = *(const uint32_t*)(sm + SB_H + n * KP + kq + 8);
                uint32_t bl0 = *(const uint32_t*)(sm + SB_L + n * KP + kq);
                uint32_t bl1 = *(const uint32_t*)(sm + SB_L + n * KP + kq + 8);
                mma_bf16(acc[nt], ah0, ah1, ah2, ah3, bh0, bh1);
                mma_bf16(acc[nt], ah0, ah1, ah2, ah3, bl0, bl1);
                mma_bf16(acc[nt], al0, al1, al2, al3, bh0, bh1);
            }
        }
    }

    float ss0 = 0.0f, ss1 = 0.0f;
    #pragma unroll
    for (int nt = 0; nt < 8; nt++) {
        int c = nt * 8 + (lane & 3) * 2;
        float b0 = __ldg(bias + c), b1 = __ldg(bias + c + 1);
        acc[nt][0] += b0; acc[nt][1] += b1;
        acc[nt][2] += b0; acc[nt][3] += b1;
        ss0 += acc[nt][0] * acc[nt][0] + acc[nt][1] * acc[nt][1];
        ss1 += acc[nt][2] * acc[nt][2] + acc[nt][3] * acc[nt][3];
    }
    ss0 += __shfl_xor_sync(0xffffffffu, ss0, 1);
    ss0 += __shfl_xor_sync(0xffffffffu, ss0, 2);
    ss1 += __shfl_xor_sync(0xffffffffu, ss1, 1);
    ss1 += __shfl_xor_sync(0xffffffffu, ss1, 2);
    float sc0 = INV_SQRT2 / fmaxf(sqrtf(ss0), 1e-12f);
    float sc1 = INV_SQRT2 / fmaxf(sqrtf(ss1), 1e-12f);
    int gr0 = rowbase + r0, gr1 = gr0 + 8;
    #pragma unroll
    for (int nt = 0; nt < 8; nt++) {
        int c = nt * 8 + (lane & 3) * 2;
        if (gr0 < M)
            *(float2*)(outp + (size_t)gr0 * DIM + BR + c) =
                make_float2(acc[nt][0] * sc0, acc[nt][1] * sc0);
        if (gr1 < M)
            *(float2*)(outp + (size_t)gr1 * DIM + BR + c) =
                make_float2(acc[nt][2] * sc1, acc[nt][3] * sc1);
    }
}

// ---------------- scoring: block per batch row ----------------
__global__ void k_score(const int* __restrict__ pos_iids, const int* __restrict__ cand_ids) {
    __shared__ __align__(16) float su[128];
    __shared__ float sc[128];
    int b = blockIdx.x, t = threadIdx.x;
    su[t] = g_batch_u[(size_t)b * DIM + t];
    __syncthreads();
    int pos = pos_iids[b];
    int id = cand_ids[(size_t)b * NCAND + t];
    if (id == pos) id = (id + 1) % N_ITEMS;
    const float4* ip = (const float4*)(g_i_all + (size_t)id * DIM);
    const float4* us = (const float4*)su;
    float a = 0.0f;
    #pragma unroll
    for (int j = 0; j < 32; j++) {
        float4 iv = __ldg(ip + j);
        float4 uv = us[j];
        a += iv.x * uv.x + iv.y * uv.y + iv.z * uv.z + iv.w * uv.w;
    }
    sc[t] = a;
    __syncthreads();

    if (t < 32) {
        const float* pp = g_i_all + (size_t)pos * DIM;
        float p = pp[t] * su[t] + pp[t + 32] * su[t + 32] +
                  pp[t + 64] * su[t + 64] + pp[t + 96] * su[t + 96];
        #pragma unroll
        for (int off = 16; off > 0; off >>= 1) p += __shfl_xor_sync(0xffffffffu, p, off);

        float v0 = sc[t * 4], v1 = sc[t * 4 + 1], v2 = sc[t * 4 + 2], v3 = sc[t * 4 + 3];
        float Lmax = 0.0f, S = 0.0f;
        for (int it = 0; it < NNEG; it++) {
            float best = v0; int bq = 0;
            if (v1 > best) { best = v1; bq = 1; }
            if (v2 > best) { best = v2; bq = 2; }
            if (v3 > best) { best = v3; bq = 3; }
            float wb = best;
            #pragma unroll
            for (int off = 16; off > 0; off >>= 1) wb = fmaxf(wb, __shfl_xor_sync(0xffffffffu, wb, off));
            unsigned m = __ballot_sync(0xffffffffu, best == wb);
            int owner = __ffs(m) - 1;
            if (t == owner) {
                if (bq == 0) v0 = -3.0e38f;
                else if (bq == 1) v1 = -3.0e38f;
                else if (bq == 2) v2 = -3.0e38f;
                else v3 = -3.0e38f;
            }
            float l = wb * 10.0f;
            if (it == 0) { Lmax = l; S = 1.0f; }
            else S += __expf(l - Lmax);
        }
        float lp = p * 10.0f;
        if (lp > Lmax) { S = S * __expf(Lmax - lp) + 1.0f; Lmax = lp; }
        else S += __expf(lp - Lmax);
        float lossb = Lmax + logf(S) - lp;
        if (t == 0) atomicAdd(&g_loss, lossb);
    }
}

__global__ void k_final(float* out) {
    out[0] = g_loss * (1.0f / (float)BATCHB);
}

// ---------------- launch ----------------
extern "C" void kernel_launch(void* const* d_in, const int* in_sizes, int n_in,
                              void* d_out, int out_size) {
    const float* raw_item_embs = (const float*)d_in[0];
    const float* user_sem_base = (const float*)d_in[1];
    const float* sem_w         = (const float*)d_in[2];
    const float* sem_b         = (const float*)d_in[3];
    const float* collab_user_w = (const float*)d_in[4];
    const float* collab_item_w = (const float*)d_in[5];
    const float* adj_vals      = (const float*)d_in[6];
    const int*   adj_rows      = (const int*)d_in[7];
    const int*   adj_cols      = (const int*)d_in[8];
    const int*   uids          = (const int*)d_in[9];
    const int*   pos_iids      = (const int*)d_in[10];
    const int*   cand_ids      = (const int*)d_in[11];
    float* out = (float*)d_out;

    cudaFuncSetAttribute(k_sem_mma<false>, cudaFuncAttributeMaxDynamicSharedMemorySize, SM_BYTES);
    cudaFuncSetAttribute(k_sem_mma<true>,  cudaFuncAttributeMaxDynamicSharedMemorySize, SM_BYTES);

    // side stream: sem GEMMs are independent of the whole GCN chain
    cudaStream_t s2;
    cudaStreamCreateWithFlags(&s2, cudaStreamNonBlocking);
    cudaEvent_t evFork, evJoin;
    cudaEventCreateWithFlags(&evFork, cudaEventDisableTiming);
    cudaEventCreateWithFlags(&evJoin, cudaEventDisableTiming);

    cudaEventRecord(evFork, 0);
    cudaStreamWaitEvent(s2, evFork, 0);
    k_sem_mma<false><<<(N_ITEMS + 127) / 128, 256, SM_BYTES, s2>>>(raw_item_embs, sem_w, sem_b,
                                                                   nullptr, N_ITEMS);
    k_sem_mma<true><<<BATCHB / 128, 256, SM_BYTES, s2>>>(user_sem_base, sem_w, sem_b,
                                                         uids, BATCHB);
    cudaEventRecord(evJoin, s2);

    // main chain
    k_zero<<<(N_TOT + 255) / 256, 256>>>();
    k_mark<<<(BATCHB + 255) / 256, 256>>>(uids);
    k_hist<<<NE / 256, 256>>>(adj_rows);
    k_scan1<<<NB_SCAN, 256>>>();
    k_scan2<<<1, 32>>>();
    k_scan3<<<NB_SCAN, 256>>>();
    k_scatter<<<NE / 256, 256>>>(adj_rows, adj_cols, adj_vals);

    int spmm_blocks = (N_TOT * 16 + 255) / 256;   // 16 threads per row now
    k_spmm<0><<<spmm_blocks, 256>>>(collab_user_w, collab_item_w);  // raw -> l1
    k_spmm<1><<<spmm_blocks, 256>>>(collab_user_w, collab_item_w);  // l1 -> l2
    k_spmm<2><<<spmm_blocks, 256>>>(collab_user_w, collab_item_w);  // l2 -> final (masked)

    k_collab_users<<<(BATCHB * 32 + 255) / 256, 256>>>(uids);

    // join: scoring needs both branches
    cudaStreamWaitEvent(0, evJoin, 0);
    k_score<<<BATCHB, 128>>>(pos_iids, cand_ids);
    k_final<<<1, 1>>>(out);

    cudaEventDestroy(evFork);
    cudaEventDestroy(evJoin);
    cudaStreamDestroy(s2);
}

// round 9
// speedup vs baseline: 1.0014x; 1.0014x over previous
#include <cuda_runtime.h>
#include <cuda_bf16.h>
#include <math.h>
#include <stdint.h>

#define N_USERS 100000
#define N_ITEMS 50000
#define N_TOT   150000
#define IN_DIM  768
#define BR      64
#define NE      2097152
#define BATCHB  4096
#define NCAND   128
#define NNEG    16
#define DIM     128
#define INV_SQRT2 0.70710678118f
#define NB_SCAN 147
#define UMARK_WORDS ((N_USERS + 31) / 32)

// ---------------- scratch (device globals; NEVER referenced from host code) ----------------
__device__ float g_l1   [(size_t)N_TOT * BR];
__device__ float g_l2   [(size_t)N_TOT * BR];
__device__ float g_acc  [(size_t)N_TOT * BR];   // only marked-user rows written (layer 3)
__device__ float g_i_all[(size_t)N_ITEMS * DIM];
__device__ float g_batch_u[(size_t)BATCHB * DIM];
__device__ int   g_row_ptr[N_TOT + 1];
__device__ int   g_row_cnt[N_TOT];
__device__ int   g_rank[NE];
__device__ int2  g_cv[NE];
__device__ int   g_bsum[256];
__device__ unsigned g_umark[UMARK_WORDS];
__device__ float g_loss;

// ---------------- zeroing ----------------
__global__ void k_zero() {                 // main chain: only what the CSR build needs
    int i = blockIdx.x * blockDim.x + threadIdx.x;
    if (i < N_TOT) g_row_cnt[i] = 0;
}

__global__ void k_zu() {                   // side stream: umark + loss
    int i = blockIdx.x * blockDim.x + threadIdx.x;
    if (i < UMARK_WORDS) g_umark[i] = 0u;
    if (i == 0) g_loss = 0.0f;
}

__global__ void k_mark(const int* __restrict__ uids) {
    int i = blockIdx.x * blockDim.x + threadIdx.x;
    if (i < BATCHB) {
        int u = uids[i];
        atomicOr(&g_umark[u >> 5], 1u << (u & 31));
    }
}

// ---------------- CSR build ----------------
// hist also records each edge's within-row rank (kills the scatter-side atomic)
__global__ void k_hist(const int* __restrict__ rows) {
    int i = blockIdx.x * blockDim.x + threadIdx.x;
    if (i < NE) g_rank[i] = atomicAdd(&g_row_cnt[rows[i]], 1);
}

__global__ void k_scan1() {
    __shared__ int red[256];
    int b = blockIdx.x, t = threadIdx.x;
    int base = b * 1024 + t * 4;
    int s = 0;
    #pragma unroll
    for (int q = 0; q < 4; q++) { int i = base + q; if (i < N_TOT) s += g_row_cnt[i]; }
    red[t] = s; __syncthreads();
    for (int off = 128; off > 0; off >>= 1) {
        if (t < off) red[t] += red[t + off];
        __syncthreads();
    }
    if (t == 0) g_bsum[b] = red[0];
}

// parallel single-block exclusive scan of the 147 block sums (was 1-thread serial ~20us)
__global__ void k_scan2() {
    __shared__ int sh[256];
    int t = threadIdx.x;
    int v = (t < NB_SCAN) ? g_bsum[t] : 0;
    sh[t] = v; __syncthreads();
    for (int off = 1; off < 256; off <<= 1) {
        int x = (t >= off) ? sh[t - off] : 0;
        __syncthreads();
        sh[t] += x;
        __syncthreads();
    }
    if (t < NB_SCAN) g_bsum[t] = sh[t] - v;   // exclusive
}

__global__ void k_scan3() {
    __shared__ int tsum[256];
    int b = blockIdx.x, t = threadIdx.x;
    int base = b * 1024 + t * 4;
    int c0 = 0, c1 = 0, c2 = 0, c3 = 0;
    if (base + 0 < N_TOT) c0 = g_row_cnt[base + 0];
    if (base + 1 < N_TOT) c1 = g_row_cnt[base + 1];
    if (base + 2 < N_TOT) c2 = g_row_cnt[base + 2];
    if (base + 3 < N_TOT) c3 = g_row_cnt[base + 3];
    int p1 = c0, p2 = c0 + c1, p3 = c0 + c1 + c2, s = p3 + c3;
    tsum[t] = s; __syncthreads();
    for (int off = 1; off < 256; off <<= 1) {
        int v = (t >= off) ? tsum[t - off] : 0;
        __syncthreads();
        tsum[t] += v;
        __syncthreads();
    }
    int excl = tsum[t] - s + g_bsum[b];
    if (base + 0 < N_TOT) g_row_ptr[base + 0] = excl;
    if (base + 1 < N_TOT) g_row_ptr[base + 1] = excl + p1;
    if (base + 2 < N_TOT) g_row_ptr[base + 2] = excl + p2;
    if (base + 3 < N_TOT) g_row_ptr[base + 3] = excl + p3;
    if (b == 0 && t == 0) g_row_ptr[N_TOT] = NE;
}

__global__ void k_scatter(const int* __restrict__ rows, const int* __restrict__ cols,
                          const float* __restrict__ vals) {
    int i = blockIdx.x * blockDim.x + threadIdx.x;
    if (i >= NE) return;
    int r = rows[i];
    g_cv[g_row_ptr[r] + g_rank[i]] = make_int2(cols[i], __float_as_int(vals[i]));
}

// ---------------- SpMM: HALF-WARP per destination row, float4 gathers ----------------
template<int MODE>
__global__ void k_spmm(const float* __restrict__ uw, const float* __restrict__ iw) {
    int tid = blockIdx.x * blockDim.x + threadIdx.x;
    int w = tid >> 4;
    int l = threadIdx.x & 15;
    int half16 = threadIdx.x & 16;

    bool valid = (w < N_TOT);
    if (MODE == 2 && valid && w < N_USERS && !((g_umark[w >> 5] >> (w & 31)) & 1u))
        valid = false;

    int s = 0, e = 0;
    if (valid) { s = g_row_ptr[w]; e = g_row_ptr[w + 1]; }
    int len = e - s;
    int olen = __shfl_xor_sync(0xffffffffu, len, 16);
    int maxlen = max(len, olen);

    float a0 = 0.0f, a1 = 0.0f, a2 = 0.0f, a3 = 0.0f;

    for (int base = 0; base < maxlen; base += 16) {
        int idx = s + base + l;
        int c = 0; float v = 0.0f;
        if (idx < e) { int2 cv = __ldg(&g_cv[idx]); c = cv.x; v = __int_as_float(cv.y); }
        int cnt = len - base; cnt = min(16, max(cnt, 0));
        int ocnt = __shfl_xor_sync(0xffffffffu, cnt, 16);
        int m4 = (max(cnt, ocnt) + 3) & ~3;
        for (int j = 0; j < m4; j += 4) {
            int cc0 = __shfl_sync(0xffffffffu, c, half16 + j);
            int cc1 = __shfl_sync(0xffffffffu, c, half16 + j + 1);
            int cc2 = __shfl_sync(0xffffffffu, c, half16 + j + 2);
            int cc3 = __shfl_sync(0xffffffffu, c, half16 + j + 3);
            float vv0 = __shfl_sync(0xffffffffu, v, half16 + j);
            float vv1 = __shfl_sync(0xffffffffu, v, half16 + j + 1);
            float vv2 = __shfl_sync(0xffffffffu, v, half16 + j + 2);
            float vv3 = __shfl_sync(0xffffffffu, v, half16 + j + 3);
            const float *b0, *b1, *b2, *b3;
            if (MODE == 0) {
                b0 = (cc0 < N_USERS) ? uw + (size_t)cc0 * BR : iw + (size_t)(cc0 - N_USERS) * BR;
                b1 = (cc1 < N_USERS) ? uw + (size_t)cc1 * BR : iw + (size_t)(cc1 - N_USERS) * BR;
                b2 = (cc2 < N_USERS) ? uw + (size_t)cc2 * BR : iw + (size_t)(cc2 - N_USERS) * BR;
                b3 = (cc3 < N_USERS) ? uw + (size_t)cc3 * BR : iw + (size_t)(cc3 - N_USERS) * BR;
            } else {
                const float* in = (MODE == 1) ? g_l1 : g_l2;
                b0 = in + (size_t)cc0 * BR;
                b1 = in + (size_t)cc1 * BR;
                b2 = in + (size_t)cc2 * BR;
                b3 = in + (size_t)cc3 * BR;
            }
            float4 p0 = __ldg((const float4*)b0 + l);
            float4 p1 = __ldg((const float4*)b1 + l);
            float4 p2 = __ldg((const float4*)b2 + l);
            float4 p3 = __ldg((const float4*)b3 + l);
            a0 = fmaf(vv0, p0.x, a0); a1 = fmaf(vv0, p0.y, a1);
            a2 = fmaf(vv0, p0.z, a2); a3 = fmaf(vv0, p0.w, a3);
            a0 = fmaf(vv1, p1.x, a0); a1 = fmaf(vv1, p1.y, a1);
            a2 = fmaf(vv1, p1.z, a2); a3 = fmaf(vv1, p1.w, a3);
            a0 = fmaf(vv2, p2.x, a0); a1 = fmaf(vv2, p2.y, a1);
            a2 = fmaf(vv2, p2.z, a2); a3 = fmaf(vv2, p2.w, a3);
            a0 = fmaf(vv3, p3.x, a0); a1 = fmaf(vv3, p3.y, a1);
            a2 = fmaf(vv3, p3.z, a2); a3 = fmaf(vv3, p3.w, a3);
        }
    }

    if (MODE == 2) {
        float t0 = 0, t1 = 0, t2 = 0, t3 = 0;
        if (valid) {
            const float* rp = (w < N_USERS) ? uw + (size_t)w * BR
                                            : iw + (size_t)(w - N_USERS) * BR;
            float4 r  = __ldg((const float4*)rp + l);
            float4 x1 = *((const float4*)(g_l1 + (size_t)w * BR) + l);
            float4 x2 = *((const float4*)(g_l2 + (size_t)w * BR) + l);
            t0 = r.x + x1.x + x2.x + a0;
            t1 = r.y + x1.y + x2.y + a1;
            t2 = r.z + x1.z + x2.z + a2;
            t3 = r.w + x1.w + x2.w + a3;
        }
        float ss = t0 * t0 + t1 * t1 + t2 * t2 + t3 * t3;
        #pragma unroll
        for (int off = 8; off > 0; off >>= 1)
            ss += __shfl_xor_sync(0xffffffffu, ss, off);
        if (valid) {
            if (w < N_USERS) {
                *((float4*)(g_acc + (size_t)w * BR) + l) = make_float4(t0, t1, t2, t3);
            } else {
                float sc = INV_SQRT2 / fmaxf(sqrtf(ss), 1e-12f);
                float* op = g_i_all + (size_t)(w - N_USERS) * DIM;
                *((float4*)op + l) = make_float4(t0 * sc, t1 * sc, t2 * sc, t3 * sc);
            }
        }
    } else if (valid) {
        float* op = (MODE == 0) ? g_l1 : g_l2;
        *((float4*)(op + (size_t)w * BR) + l) = make_float4(a0, a1, a2, a3);
    }
}

__global__ void k_collab_users(const int* __restrict__ uids) {
    int w = (blockIdx.x * blockDim.x + threadIdx.x) >> 5;
    int lane = threadIdx.x & 31;
    if (w >= BATCHB) return;
    int u = uids[w];
    size_t o = (size_t)u * BR;
    float v0 = g_acc[o + lane], v1 = g_acc[o + lane + 32];
    float ss = v0 * v0 + v1 * v1;
    #pragma unroll
    for (int off = 16; off > 0; off >>= 1) ss += __shfl_xor_sync(0xffffffffu, ss, off);
    float sc = INV_SQRT2 / fmaxf(sqrtf(ss), 1e-12f);
    g_batch_u[(size_t)w * DIM + lane] = v0 * sc;
    g_batch_u[(size_t)w * DIM + lane + 32] = v1 * sc;
}

// ---------------- split-bf16 mma.sync semantic GEMM ----------------
#define KC 64
#define KP 72
#define NCHUNKS (IN_DIM / KC)
#define SA_H 0
#define SA_L (128 * KP)
#define SB_H (2 * 128 * KP)
#define SB_L (2 * 128 * KP + 64 * KP)
#define SM_U16_TOTAL (2 * 128 * KP + 2 * 64 * KP)
#define SM_BYTES (SM_U16_TOTAL * 2)

__device__ __forceinline__ void mma_bf16(float* d, uint32_t a0, uint32_t a1, uint32_t a2,
                                         uint32_t a3, uint32_t b0, uint32_t b1) {
    asm volatile("mma.sync.aligned.m16n8k16.row.col.f32.bf16.bf16.f32 "
                 "{%0,%1,%2,%3}, {%4,%5,%6,%7}, {%8,%9}, {%0,%1,%2,%3};"
                 : "+f"(d[0]), "+f"(d[1]), "+f"(d[2]), "+f"(d[3])
                 : "r"(a0), "r"(a1), "r"(a2), "r"(a3), "r"(b0), "r"(b1));
}

__device__ __forceinline__ void split2(float x, float y, uint32_t& hi, uint32_t& lo) {
    uint32_t xi = __float_as_uint(x), yi = __float_as_uint(y);
    hi = __byte_perm(xi, yi, 0x7632);
    float lx = x - __uint_as_float(xi & 0xFFFF0000u);
    float ly = y - __uint_as_float(yi & 0xFFFF0000u);
    __nv_bfloat162 p = __floats2bfloat162_rn(lx, ly);
    lo = *(uint32_t*)&p;
}

template<bool GATHER>
__global__ void __launch_bounds__(256) k_sem_mma(const float* __restrict__ A,
                                                 const float* __restrict__ W,
                                                 const float* __restrict__ bias,
                                                 const int* __restrict__ gidx, int M) {
    extern __shared__ uint16_t sm[];
    float* __restrict__ outp = GATHER ? g_batch_u : g_i_all;
    int t = threadIdx.x, wid = t >> 5, lane = t & 31;
    int rowbase = blockIdx.x * 128;

    int ar = t >> 1, kh = (t & 1) * 32;
    int gr = rowbase + ar;
    bool av = gr < M;
    int srow = av ? (GATHER ? __ldg(gidx + gr) : gr) : 0;
    const float* arp = A + (size_t)srow * IN_DIM;

    int bn = t & 63, bk0 = t >> 6;

    float acc[8][4];
    #pragma unroll
    for (int i = 0; i < 8; i++)
        #pragma unroll
        for (int j = 0; j < 4; j++) acc[i][j] = 0.0f;

    int mr = wid * 16;
    int r0 = mr + (lane >> 2);
    int kq0 = (lane & 3) * 2;

    for (int ch = 0; ch < NCHUNKS; ch++) {
        int k0 = ch * KC;
        __syncthreads();
        #pragma unroll
        for (int i = 0; i < 8; i++) {
            int k = kh + i * 4;
            float4 a = av ? __ldg((const float4*)(arp + k0 + k)) : make_float4(0, 0, 0, 0);
            uint32_t h01, l01, h23, l23;
            split2(a.x, a.y, h01, l01);
            split2(a.z, a.w, h23, l23);
            int o = ar * KP + k;
            *(uint32_t*)(sm + SA_H + o)     = h01;
            *(uint32_t*)(sm + SA_H + o + 2) = h23;
            *(uint32_t*)(sm + SA_L + o)     = l01;
            *(uint32_t*)(sm + SA_L + o + 2) = l23;
        }
        #pragma unroll
        for (int i = 0; i < 16; i++) {
            int k = bk0 + i * 4;
            float wv = __ldg(W + (size_t)(k0 + k) * BR + bn);
            uint32_t wi = __float_as_uint(wv);
            float lo = wv - __uint_as_float(wi & 0xFFFF0000u);
            __nv_bfloat16 bl = __float2bfloat16(lo);
            int o = bn * KP + k;
            sm[SB_H + o] = (uint16_t)(wi >> 16);
            sm[SB_L + o] = *(uint16_t*)&bl;
        }
        __syncthreads();
        #pragma unroll
        for (int ks = 0; ks < 4; ks++) {
            int kq = ks * 16 + kq0;
            const uint16_t* pah = sm + SA_H + kq;
            const uint16_t* pal = sm + SA_L + kq;
            uint32_t ah0 = *(const uint32_t*)(pah + r0 * KP);
            uint32_t ah1 = *(const uint32_t*)(pah + (r0 + 8) * KP);
            uint32_t ah2 = *(const uint32_t*)(pah + r0 * KP + 8);
            uint32_t ah3 = *(const uint32_t*)(pah + (r0 + 8) * KP + 8);
            uint32_t al0 = *(const uint32_t*)(pal + r0 * KP);
            uint32_t al1 = *(const uint32_t*)(pal + (r0 + 8) * KP);
            uint32_t al2 = *(const uint32_t*)(pal + r0 * KP + 8);
            uint32_t al3 = *(const uint32_t*)(pal + (r0 + 8) * KP + 8);
            #pragma unroll
            for (int nt = 0; nt < 8; nt++) {
                int n = nt * 8 + (lane >> 2);
                uint32_t bh0 = *(const uint32_t*)(sm + SB_H + n * KP + kq);
                uint32_t bh1 = *(const uint32_t*)(sm + SB_H + n * KP + kq + 8);
                uint32_t bl0 = *(const uint32_t*)(sm + SB_L + n * KP + kq);
                uint32_t bl1 = *(const uint32_t*)(sm + SB_L + n * KP + kq + 8);
                mma_bf16(acc[nt], ah0, ah1, ah2, ah3, bh0, bh1);
                mma_bf16(acc[nt], ah0, ah1, ah2, ah3, bl0, bl1);
                mma_bf16(acc[nt], al0, al1, al2, al3, bh0, bh1);
            }
        }
    }

    float ss0 = 0.0f, ss1 = 0.0f;
    #pragma unroll
    for (int nt = 0; nt < 8; nt++) {
        int c = nt * 8 + (lane & 3) * 2;
        float b0 = __ldg(bias + c), b1 = __ldg(bias + c + 1);
        acc[nt][0] += b0; acc[nt][1] += b1;
        acc[nt][2] += b0; acc[nt][3] += b1;
        ss0 += acc[nt][0] * acc[nt][0] + acc[nt][1] * acc[nt][1];
        ss1 += acc[nt][2] * acc[nt][2] + acc[nt][3] * acc[nt][3];
    }
    ss0 += __shfl_xor_sync(0xffffffffu, ss0, 1);
    ss0 += __shfl_xor_sync(0xffffffffu, ss0, 2);
    ss1 += __shfl_xor_sync(0xffffffffu, ss1, 1);
    ss1 += __shfl_xor_sync(0xffffffffu, ss1, 2);
    float sc0 = INV_SQRT2 / fmaxf(sqrtf(ss0), 1e-12f);
    float sc1 = INV_SQRT2 / fmaxf(sqrtf(ss1), 1e-12f);
    int gr0 = rowbase + r0, gr1 = gr0 + 8;
    #pragma unroll
    for (int nt = 0; nt < 8; nt++) {
        int c = nt * 8 + (lane & 3) * 2;
        if (gr0 < M)
            *(float2*)(outp + (size_t)gr0 * DIM + BR + c) =
                make_float2(acc[nt][0] * sc0, acc[nt][1] * sc0);
        if (gr1 < M)
            *(float2*)(outp + (size_t)gr1 * DIM + BR + c) =
                make_float2(acc[nt][2] * sc1, acc[nt][3] * sc1);
    }
}

// ---------------- scoring: block per batch row ----------------
__global__ void k_score(const int* __restrict__ pos_iids, const int* __restrict__ cand_ids) {
    __shared__ __align__(16) float su[128];
    __shared__ float sc[128];
    int b = blockIdx.x, t = threadIdx.x;
    su[t] = g_batch_u[(size_t)b * DIM + t];
    __syncthreads();
    int pos = pos_iids[b];
    int id = cand_ids[(size_t)b * NCAND + t];
    if (id == pos) id = (id + 1) % N_ITEMS;
    const float4* ip = (const float4*)(g_i_all + (size_t)id * DIM);
    const float4* us = (const float4*)su;
    float a = 0.0f;
    #pragma unroll
    for (int j = 0; j < 32; j++) {
        float4 iv = __ldg(ip + j);
        float4 uv = us[j];
        a += iv.x * uv.x + iv.y * uv.y + iv.z * uv.z + iv.w * uv.w;
    }
    sc[t] = a;
    __syncthreads();

    if (t < 32) {
        const float* pp = g_i_all + (size_t)pos * DIM;
        float p = pp[t] * su[t] + pp[t + 32] * su[t + 32] +
                  pp[t + 64] * su[t + 64] + pp[t + 96] * su[t + 96];
        #pragma unroll
        for (int off = 16; off > 0; off >>= 1) p += __shfl_xor_sync(0xffffffffu, p, off);

        float v0 = sc[t * 4], v1 = sc[t * 4 + 1], v2 = sc[t * 4 + 2], v3 = sc[t * 4 + 3];
        float Lmax = 0.0f, S = 0.0f;
        for (int it = 0; it < NNEG; it++) {
            float best = v0; int bq = 0;
            if (v1 > best) { best = v1; bq = 1; }
            if (v2 > best) { best = v2; bq = 2; }
            if (v3 > best) { best = v3; bq = 3; }
            float wb = best;
            #pragma unroll
            for (int off = 16; off > 0; off >>= 1) wb = fmaxf(wb, __shfl_xor_sync(0xffffffffu, wb, off));
            unsigned m = __ballot_sync(0xffffffffu, best == wb);
            int owner = __ffs(m) - 1;
            if (t == owner) {
                if (bq == 0) v0 = -3.0e38f;
                else if (bq == 1) v1 = -3.0e38f;
                else if (bq == 2) v2 = -3.0e38f;
                else v3 = -3.0e38f;
            }
            float l = wb * 10.0f;
            if (it == 0) { Lmax = l; S = 1.0f; }
            else S += __expf(l - Lmax);
        }
        float lp = p * 10.0f;
        if (lp > Lmax) { S = S * __expf(Lmax - lp) + 1.0f; Lmax = lp; }
        else S += __expf(lp - Lmax);
        float lossb = Lmax + logf(S) - lp;
        if (t == 0) atomicAdd(&g_loss, lossb);
    }
}

__global__ void k_final(float* out) {
    out[0] = g_loss * (1.0f / (float)BATCHB);
}

// ---------------- launch ----------------
extern "C" void kernel_launch(void* const* d_in, const int* in_sizes, int n_in,
                              void* d_out, int out_size) {
    const float* raw_item_embs = (const float*)d_in[0];
    const float* user_sem_base = (const float*)d_in[1];
    const float* sem_w         = (const float*)d_in[2];
    const float* sem_b         = (const float*)d_in[3];
    const float* collab_user_w = (const float*)d_in[4];
    const float* collab_item_w = (const float*)d_in[5];
    const float* adj_vals      = (const float*)d_in[6];
    const int*   adj_rows      = (const int*)d_in[7];
    const int*   adj_cols      = (const int*)d_in[8];
    const int*   uids          = (const int*)d_in[9];
    const int*   pos_iids      = (const int*)d_in[10];
    const int*   cand_ids      = (const int*)d_in[11];
    float* out = (float*)d_out;

    cudaFuncSetAttribute(k_sem_mma<false>, cudaFuncAttributeMaxDynamicSharedMemorySize, SM_BYTES);
    cudaFuncSetAttribute(k_sem_mma<true>,  cudaFuncAttributeMaxDynamicSharedMemorySize, SM_BYTES);

    cudaStream_t s2;
    cudaStreamCreateWithFlags(&s2, cudaStreamNonBlocking);
    cudaEvent_t evFork, evMark, evJoin;
    cudaEventCreateWithFlags(&evFork, cudaEventDisableTiming);
    cudaEventCreateWithFlags(&evMark, cudaEventDisableTiming);
    cudaEventCreateWithFlags(&evJoin, cudaEventDisableTiming);

    cudaEventRecord(evFork, 0);
    cudaStreamWaitEvent(s2, evFork, 0);

    // side stream: umark/loss zero + mark, then the independent sem GEMMs
    k_zu<<<(UMARK_WORDS + 255) / 256, 256, 0, s2>>>();
    k_mark<<<(BATCHB + 255) / 256, 256, 0, s2>>>(uids);
    cudaEventRecord(evMark, s2);
    k_sem_mma<false><<<(N_ITEMS + 127) / 128, 256, SM_BYTES, s2>>>(raw_item_embs, sem_w, sem_b,
                                                                   nullptr, N_ITEMS);
    k_sem_mma<true><<<BATCHB / 128, 256, SM_BYTES, s2>>>(user_sem_base, sem_w, sem_b,
                                                         uids, BATCHB);
    cudaEventRecord(evJoin, s2);

    // main chain: CSR build + GCN
    k_zero<<<(N_TOT + 255) / 256, 256>>>();
    k_hist<<<NE / 256, 256>>>(adj_rows);
    k_scan1<<<NB_SCAN, 256>>>();
    k_scan2<<<1, 256>>>();
    k_scan3<<<NB_SCAN, 256>>>();
    k_scatter<<<NE / 256, 256>>>(adj_rows, adj_cols, adj_vals);

    int spmm_blocks = (N_TOT * 16 + 255) / 256;
    k_spmm<0><<<spmm_blocks, 256>>>(collab_user_w, collab_item_w);
    k_spmm<1><<<spmm_blocks, 256>>>(collab_user_w, collab_item_w);
    cudaStreamWaitEvent(0, evMark, 0);   // spmm<2> reads g_umark
    k_spmm<2><<<spmm_blocks, 256>>>(collab_user_w, collab_item_w);

    k_collab_users<<<(BATCHB * 32 + 255) / 256, 256>>>(uids);

    cudaStreamWaitEvent(0, evJoin, 0);   // score needs sem halves + g_loss zeroed
    k_score<<<BATCHB, 128>>>(pos_iids, cand_ids);
    k_final<<<1, 1>>>(out);

    cudaEventDestroy(evFork);
    cudaEventDestroy(evMark);
    cudaEventDestroy(evJoin);
    cudaStreamDestroy(s2);
}

// round 10
// speedup vs baseline: 1.0352x; 1.0337x over previous
#include <cuda_runtime.h>
#include <cuda_bf16.h>
#include <cuda_fp16.h>
#include <math.h>
#include <stdint.h>

#define N_USERS 100000
#define N_ITEMS 50000
#define N_TOT   150000
#define IN_DIM  768
#define BR      64
#define NE      2097152
#define BATCHB  4096
#define NCAND   128
#define NNEG    16
#define DIM     128
#define INV_SQRT2 0.70710678118f
#define NB_SCAN 147
#define UMARK_WORDS ((N_USERS + 31) / 32)

// ---------------- scratch (device globals; NEVER referenced from host code) ----------------
__device__ __half2 g_l0h[(size_t)N_TOT * 32];   // fp16 copy of raw ego
__device__ __half2 g_l1h[(size_t)N_TOT * 32];   // layer-1 out (fp16)
__device__ __half2 g_l2h[(size_t)N_TOT * 32];   // layer-2 out (fp16)
__device__ float g_acc  [(size_t)N_TOT * BR];   // only marked-user rows written (layer 3)
__device__ float g_i_all[(size_t)N_ITEMS * DIM];
__device__ float g_batch_u[(size_t)BATCHB * DIM];
__device__ int   g_row_ptr[N_TOT + 1];
__device__ int   g_row_cnt[N_TOT];
__device__ int   g_rank[NE];
__device__ int2  g_cv[NE];
__device__ int   g_bsum[256];
__device__ unsigned g_umark[UMARK_WORDS];
__device__ float g_loss;

// ---------------- zeroing / marking ----------------
__global__ void k_zero() {
    int i = blockIdx.x * blockDim.x + threadIdx.x;
    if (i < N_TOT) g_row_cnt[i] = 0;
}

__global__ void k_zu() {
    int i = blockIdx.x * blockDim.x + threadIdx.x;
    if (i < UMARK_WORDS) g_umark[i] = 0u;
    if (i == 0) g_loss = 0.0f;
}

__global__ void k_mark(const int* __restrict__ uids) {
    int i = blockIdx.x * blockDim.x + threadIdx.x;
    if (i < BATCHB) {
        int u = uids[i];
        atomicOr(&g_umark[u >> 5], 1u << (u & 31));
    }
}

// convert raw ego to fp16 (streamed)
__global__ void k_conv(const float* __restrict__ uw, const float* __restrict__ iw) {
    int i = blockIdx.x * blockDim.x + threadIdx.x;     // one half2 (2 floats) per thread
    if (i >= N_TOT * 32) return;
    int idx2 = i * 2;
    int row = idx2 >> 6, c = idx2 & 63;
    const float* src = (row < N_USERS) ? uw + (size_t)row * BR
                                       : iw + (size_t)(row - N_USERS) * BR;
    float2 v = *(const float2*)(src + c);
    g_l0h[i] = __floats2half2_rn(v.x, v.y);
}

// ---------------- CSR build ----------------
__global__ void k_hist(const int* __restrict__ rows) {
    int i = blockIdx.x * blockDim.x + threadIdx.x;
    if (i < NE) g_rank[i] = atomicAdd(&g_row_cnt[rows[i]], 1);
}

__global__ void k_scan1() {
    __shared__ int red[256];
    int b = blockIdx.x, t = threadIdx.x;
    int base = b * 1024 + t * 4;
    int s = 0;
    #pragma unroll
    for (int q = 0; q < 4; q++) { int i = base + q; if (i < N_TOT) s += g_row_cnt[i]; }
    red[t] = s; __syncthreads();
    for (int off = 128; off > 0; off >>= 1) {
        if (t < off) red[t] += red[t + off];
        __syncthreads();
    }
    if (t == 0) g_bsum[b] = red[0];
}

__global__ void k_scan2() {
    __shared__ int sh[256];
    int t = threadIdx.x;
    int v = (t < NB_SCAN) ? g_bsum[t] : 0;
    sh[t] = v; __syncthreads();
    for (int off = 1; off < 256; off <<= 1) {
        int x = (t >= off) ? sh[t - off] : 0;
        __syncthreads();
        sh[t] += x;
        __syncthreads();
    }
    if (t < NB_SCAN) g_bsum[t] = sh[t] - v;
}

__global__ void k_scan3() {
    __shared__ int tsum[256];
    int b = blockIdx.x, t = threadIdx.x;
    int base = b * 1024 + t * 4;
    int c0 = 0, c1 = 0, c2 = 0, c3 = 0;
    if (base + 0 < N_TOT) c0 = g_row_cnt[base + 0];
    if (base + 1 < N_TOT) c1 = g_row_cnt[base + 1];
    if (base + 2 < N_TOT) c2 = g_row_cnt[base + 2];
    if (base + 3 < N_TOT) c3 = g_row_cnt[base + 3];
    int p1 = c0, p2 = c0 + c1, p3 = c0 + c1 + c2, s = p3 + c3;
    tsum[t] = s; __syncthreads();
    for (int off = 1; off < 256; off <<= 1) {
        int v = (t >= off) ? tsum[t - off] : 0;
        __syncthreads();
        tsum[t] += v;
        __syncthreads();
    }
    int excl = tsum[t] - s + g_bsum[b];
    if (base + 0 < N_TOT) g_row_ptr[base + 0] = excl;
    if (base + 1 < N_TOT) g_row_ptr[base + 1] = excl + p1;
    if (base + 2 < N_TOT) g_row_ptr[base + 2] = excl + p2;
    if (base + 3 < N_TOT) g_row_ptr[base + 3] = excl + p3;
    if (b == 0 && t == 0) g_row_ptr[N_TOT] = NE;
}

__global__ void k_scatter(const int* __restrict__ rows, const int* __restrict__ cols,
                          const float* __restrict__ vals) {
    int i = blockIdx.x * blockDim.x + threadIdx.x;
    if (i >= NE) return;
    int r = rows[i];
    g_cv[g_row_ptr[r] + g_rank[i]] = make_int2(cols[i], __float_as_int(vals[i]));
}

// ---------------- SpMM: half-warp per row, fp16 gathers ----------------
// MODE 0: gather g_l0h -> g_l1h ; MODE 1: gather g_l1h -> g_l2h
// MODE 2: gather g_l2h; epilogue acc = raw(fp32) + l1 + l2 + l3;
//         items -> g_i_all normalized, marked users -> g_acc.
template<int MODE>
__global__ void k_spmm(const float* __restrict__ uw, const float* __restrict__ iw) {
    int tid = blockIdx.x * blockDim.x + threadIdx.x;
    int w = tid >> 4;
    int l = threadIdx.x & 15;
    int half16 = threadIdx.x & 16;

    bool valid = (w < N_TOT);
    if (MODE == 2 && valid && w < N_USERS && !((g_umark[w >> 5] >> (w & 31)) & 1u))
        valid = false;

    int s = 0, e = 0;
    if (valid) { s = g_row_ptr[w]; e = g_row_ptr[w + 1]; }
    int len = e - s;
    int olen = __shfl_xor_sync(0xffffffffu, len, 16);
    int maxlen = max(len, olen);

    const __half2* __restrict__ in = (MODE == 0) ? g_l0h : (MODE == 1) ? g_l1h : g_l2h;

    float a0 = 0.0f, a1 = 0.0f, a2 = 0.0f, a3 = 0.0f;

    for (int base = 0; base < maxlen; base += 16) {
        int idx = s + base + l;
        int c = 0; float v = 0.0f;
        if (idx < e) { int2 cv = __ldg(&g_cv[idx]); c = cv.x; v = __int_as_float(cv.y); }
        int cnt = len - base; cnt = min(16, max(cnt, 0));
        int ocnt = __shfl_xor_sync(0xffffffffu, cnt, 16);
        int m4 = (max(cnt, ocnt) + 3) & ~3;
        for (int j = 0; j < m4; j += 4) {
            int cc0 = __shfl_sync(0xffffffffu, c, half16 + j);
            int cc1 = __shfl_sync(0xffffffffu, c, half16 + j + 1);
            int cc2 = __shfl_sync(0xffffffffu, c, half16 + j + 2);
            int cc3 = __shfl_sync(0xffffffffu, c, half16 + j + 3);
            float vv0 = __shfl_sync(0xffffffffu, v, half16 + j);
            float vv1 = __shfl_sync(0xffffffffu, v, half16 + j + 1);
            float vv2 = __shfl_sync(0xffffffffu, v, half16 + j + 2);
            float vv3 = __shfl_sync(0xffffffffu, v, half16 + j + 3);
            uint2 q0 = __ldg((const uint2*)(in + (size_t)cc0 * 32) + l);
            uint2 q1 = __ldg((const uint2*)(in + (size_t)cc1 * 32) + l);
            uint2 q2 = __ldg((const uint2*)(in + (size_t)cc2 * 32) + l);
            uint2 q3 = __ldg((const uint2*)(in + (size_t)cc3 * 32) + l);
            float2 f;
            f = __half22float2(*(__half2*)&q0.x); a0 = fmaf(vv0, f.x, a0); a1 = fmaf(vv0, f.y, a1);
            f = __half22float2(*(__half2*)&q0.y); a2 = fmaf(vv0, f.x, a2); a3 = fmaf(vv0, f.y, a3);
            f = __half22float2(*(__half2*)&q1.x); a0 = fmaf(vv1, f.x, a0); a1 = fmaf(vv1, f.y, a1);
            f = __half22float2(*(__half2*)&q1.y); a2 = fmaf(vv1, f.x, a2); a3 = fmaf(vv1, f.y, a3);
            f = __half22float2(*(__half2*)&q2.x); a0 = fmaf(vv2, f.x, a0); a1 = fmaf(vv2, f.y, a1);
            f = __half22float2(*(__half2*)&q2.y); a2 = fmaf(vv2, f.x, a2); a3 = fmaf(vv2, f.y, a3);
            f = __half22float2(*(__half2*)&q3.x); a0 = fmaf(vv3, f.x, a0); a1 = fmaf(vv3, f.y, a1);
            f = __half22float2(*(__half2*)&q3.y); a2 = fmaf(vv3, f.x, a2); a3 = fmaf(vv3, f.y, a3);
        }
    }

    if (MODE == 2) {
        float t0 = 0, t1 = 0, t2 = 0, t3 = 0;
        if (valid) {
            const float* rp = (w < N_USERS) ? uw + (size_t)w * BR
                                            : iw + (size_t)(w - N_USERS) * BR;
            float4 r = __ldg((const float4*)rp + l);
            uint2 q1 = *((const uint2*)(g_l1h + (size_t)w * 32) + l);
            uint2 q2 = *((const uint2*)(g_l2h + (size_t)w * 32) + l);
            float2 x1a = __half22float2(*(__half2*)&q1.x);
            float2 x1b = __half22float2(*(__half2*)&q1.y);
            float2 x2a = __half22float2(*(__half2*)&q2.x);
            float2 x2b = __half22float2(*(__half2*)&q2.y);
            t0 = r.x + x1a.x + x2a.x + a0;
            t1 = r.y + x1a.y + x2a.y + a1;
            t2 = r.z + x1b.x + x2b.x + a2;
            t3 = r.w + x1b.y + x2b.y + a3;
        }
        float ss = t0 * t0 + t1 * t1 + t2 * t2 + t3 * t3;
        #pragma unroll
        for (int off = 8; off > 0; off >>= 1)
            ss += __shfl_xor_sync(0xffffffffu, ss, off);
        if (valid) {
            if (w < N_USERS) {
                *((float4*)(g_acc + (size_t)w * BR) + l) = make_float4(t0, t1, t2, t3);
            } else {
                float sc = INV_SQRT2 / fmaxf(sqrtf(ss), 1e-12f);
                float* op = g_i_all + (size_t)(w - N_USERS) * DIM;
                *((float4*)op + l) = make_float4(t0 * sc, t1 * sc, t2 * sc, t3 * sc);
            }
        }
    } else if (valid) {
        __half2* op = (MODE == 0) ? g_l1h : g_l2h;
        __half2 ha = __floats2half2_rn(a0, a1);
        __half2 hb = __floats2half2_rn(a2, a3);
        uint2 q;
        q.x = *(uint32_t*)&ha;
        q.y = *(uint32_t*)&hb;
        *((uint2*)(op + (size_t)w * 32) + l) = q;
    }
}

__global__ void k_collab_users(const int* __restrict__ uids) {
    int w = (blockIdx.x * blockDim.x + threadIdx.x) >> 5;
    int lane = threadIdx.x & 31;
    if (w >= BATCHB) return;
    int u = uids[w];
    size_t o = (size_t)u * BR;
    float v0 = g_acc[o + lane], v1 = g_acc[o + lane + 32];
    float ss = v0 * v0 + v1 * v1;
    #pragma unroll
    for (int off = 16; off > 0; off >>= 1) ss += __shfl_xor_sync(0xffffffffu, ss, off);
    float sc = INV_SQRT2 / fmaxf(sqrtf(ss), 1e-12f);
    g_batch_u[(size_t)w * DIM + lane] = v0 * sc;
    g_batch_u[(size_t)w * DIM + lane + 32] = v1 * sc;
}

// ---------------- split-bf16 mma.sync semantic GEMM ----------------
#define KC 64
#define KP 72
#define NCHUNKS (IN_DIM / KC)
#define SA_H 0
#define SA_L (128 * KP)
#define SB_H (2 * 128 * KP)
#define SB_L (2 * 128 * KP + 64 * KP)
#define SM_U16_TOTAL (2 * 128 * KP + 2 * 64 * KP)
#define SM_BYTES (SM_U16_TOTAL * 2)

__device__ __forceinline__ void mma_bf16(float* d, uint32_t a0, uint32_t a1, uint32_t a2,
                                         uint32_t a3, uint32_t b0, uint32_t b1) {
    asm volatile("mma.sync.aligned.m16n8k16.row.col.f32.bf16.bf16.f32 "
                 "{%0,%1,%2,%3}, {%4,%5,%6,%7}, {%8,%9}, {%0,%1,%2,%3};"
                 : "+f"(d[0]), "+f"(d[1]), "+f"(d[2]), "+f"(d[3])
                 : "r"(a0), "r"(a1), "r"(a2), "r"(a3), "r"(b0), "r"(b1));
}

__device__ __forceinline__ void split2(float x, float y, uint32_t& hi, uint32_t& lo) {
    uint32_t xi = __float_as_uint(x), yi = __float_as_uint(y);
    hi = __byte_perm(xi, yi, 0x7632);
    float lx = x - __uint_as_float(xi & 0xFFFF0000u);
    float ly = y - __uint_as_float(yi & 0xFFFF0000u);
    __nv_bfloat162 p = __floats2bfloat162_rn(lx, ly);
    lo = *(uint32_t*)&p;
}

template<bool GATHER>
__global__ void __launch_bounds__(256) k_sem_mma(const float* __restrict__ A,
                                                 const float* __restrict__ W,
                                                 const float* __restrict__ bias,
                                                 const int* __restrict__ gidx, int M) {
    extern __shared__ uint16_t sm[];
    float* __restrict__ outp = GATHER ? g_batch_u : g_i_all;
    int t = threadIdx.x, wid = t >> 5, lane = t & 31;
    int rowbase = blockIdx.x * 128;

    int ar = t >> 1, kh = (t & 1) * 32;
    int gr = rowbase + ar;
    bool av = gr < M;
    int srow = av ? (GATHER ? __ldg(gidx + gr) : gr) : 0;
    const float* arp = A + (size_t)srow * IN_DIM;

    int bn = t & 63, bk0 = t >> 6;

    float acc[8][4];
    #pragma unroll
    for (int i = 0; i < 8; i++)
        #pragma unroll
        for (int j = 0; j < 4; j++) acc[i][j] = 0.0f;

    int mr = wid * 16;
    int r0 = mr + (lane >> 2);
    int kq0 = (lane & 3) * 2;

    for (int ch = 0; ch < NCHUNKS; ch++) {
        int k0 = ch * KC;
        __syncthreads();
        #pragma unroll
        for (int i = 0; i < 8; i++) {
            int k = kh + i * 4;
            float4 a = av ? __ldg((const float4*)(arp + k0 + k)) : make_float4(0, 0, 0, 0);
            uint32_t h01, l01, h23, l23;
            split2(a.x, a.y, h01, l01);
            split2(a.z, a.w, h23, l23);
            int o = ar * KP + k;
            *(uint32_t*)(sm + SA_H + o)     = h01;
            *(uint32_t*)(sm + SA_H + o + 2) = h23;
            *(uint32_t*)(sm + SA_L + o)     = l01;
            *(uint32_t*)(sm + SA_L + o + 2) = l23;
        }
        #pragma unroll
        for (int i = 0; i < 16; i++) {
            int k = bk0 + i * 4;
            float wv = __ldg(W + (size_t)(k0 + k) * BR + bn);
            uint32_t wi = __float_as_uint(wv);
            float lo = wv - __uint_as_float(wi & 0xFFFF0000u);
            __nv_bfloat16 bl = __float2bfloat16(lo);
            int o = bn * KP + k;
            sm[SB_H + o] = (uint16_t)(wi >> 16);
            sm[SB_L + o] = *(uint16_t*)&bl;
        }
        __syncthreads();
        #pragma unroll
        for (int ks = 0; ks < 4; ks++) {
            int kq = ks * 16 + kq0;
            const uint16_t* pah = sm + SA_H + kq;
            const uint16_t* pal = sm + SA_L + kq;
            uint32_t ah0 = *(const uint32_t*)(pah + r0 * KP);
            uint32_t ah1 = *(const uint32_t*)(pah + (r0 + 8) * KP);
            uint32_t ah2 = *(const uint32_t*)(pah + r0 * KP + 8);
            uint32_t ah3 = *(const uint32_t*)(pah + (r0 + 8) * KP + 8);
            uint32_t al0 = *(const uint32_t*)(pal + r0 * KP);
            uint32_t al1 = *(const uint32_t*)(pal + (r0 + 8) * KP);
            uint32_t al2 = *(const uint32_t*)(pal + r0 * KP + 8);
            uint32_t al3 = *(const uint32_t*)(pal + (r0 + 8) * KP + 8);
            #pragma unroll
            for (int nt = 0; nt < 8; nt++) {
                int n = nt * 8 + (lane >> 2);
                uint32_t bh0 = *(const uint32_t*)(sm + SB_H + n * KP + kq);
                uint32_t bh1 = *(const uint32_t*)(sm + SB_H + n * KP + kq + 8);
                uint32_t bl0 = *(const uint32_t*)(sm + SB_L + n * KP + kq);
                uint32_t bl1 = *(const uint32_t*)(sm + SB_L + n * KP + kq + 8);
                mma_bf16(acc[nt], ah0, ah1, ah2, ah3, bh0, bh1);
                mma_bf16(acc[nt], ah0, ah1, ah2, ah3, bl0, bl1);
                mma_bf16(acc[nt], al0, al1, al2, al3, bh0, bh1);
            }
        }
    }

    float ss0 = 0.0f, ss1 = 0.0f;
    #pragma unroll
    for (int nt = 0; nt < 8; nt++) {
        int c = nt * 8 + (lane & 3) * 2;
        float b0 = __ldg(bias + c), b1 = __ldg(bias + c + 1);
        acc[nt][0] += b0; acc[nt][1] += b1;
        acc[nt][2] += b0; acc[nt][3] += b1;
        ss0 += acc[nt][0] * acc[nt][0] + acc[nt][1] * acc[nt][1];
        ss1 += acc[nt][2] * acc[nt][2] + acc[nt][3] * acc[nt][3];
    }
    ss0 += __shfl_xor_sync(0xffffffffu, ss0, 1);
    ss0 += __shfl_xor_sync(0xffffffffu, ss0, 2);
    ss1 += __shfl_xor_sync(0xffffffffu, ss1, 1);
    ss1 += __shfl_xor_sync(0xffffffffu, ss1, 2);
    float sc0 = INV_SQRT2 / fmaxf(sqrtf(ss0), 1e-12f);
    float sc1 = INV_SQRT2 / fmaxf(sqrtf(ss1), 1e-12f);
    int gr0 = rowbase + r0, gr1 = gr0 + 8;
    #pragma unroll
    for (int nt = 0; nt < 8; nt++) {
        int c = nt * 8 + (lane & 3) * 2;
        if (gr0 < M)
            *(float2*)(outp + (size_t)gr0 * DIM + BR + c) =
                make_float2(acc[nt][0] * sc0, acc[nt][1] * sc0);
        if (gr1 < M)
            *(float2*)(outp + (size_t)gr1 * DIM + BR + c) =
                make_float2(acc[nt][2] * sc1, acc[nt][3] * sc1);
    }
}

// ---------------- scoring: block per batch row ----------------
__global__ void k_score(const int* __restrict__ pos_iids, const int* __restrict__ cand_ids) {
    __shared__ __align__(16) float su[128];
    __shared__ float sc[128];
    int b = blockIdx.x, t = threadIdx.x;
    su[t] = g_batch_u[(size_t)b * DIM + t];
    __syncthreads();
    int pos = pos_iids[b];
    int id = cand_ids[(size_t)b * NCAND + t];
    if (id == pos) id = (id + 1) % N_ITEMS;
    const float4* ip = (const float4*)(g_i_all + (size_t)id * DIM);
    const float4* us = (const float4*)su;
    float a = 0.0f;
    #pragma unroll
    for (int j = 0; j < 32; j++) {
        float4 iv = __ldg(ip + j);
        float4 uv = us[j];
        a += iv.x * uv.x + iv.y * uv.y + iv.z * uv.z + iv.w * uv.w;
    }
    sc[t] = a;
    __syncthreads();

    if (t < 32) {
        const float* pp = g_i_all + (size_t)pos * DIM;
        float p = pp[t] * su[t] + pp[t + 32] * su[t + 32] +
                  pp[t + 64] * su[t + 64] + pp[t + 96] * su[t + 96];
        #pragma unroll
        for (int off = 16; off > 0; off >>= 1) p += __shfl_xor_sync(0xffffffffu, p, off);

        float v0 = sc[t * 4], v1 = sc[t * 4 + 1], v2 = sc[t * 4 + 2], v3 = sc[t * 4 + 3];
        float Lmax = 0.0f, S = 0.0f;
        for (int it = 0; it < NNEG; it++) {
            float best = v0; int bq = 0;
            if (v1 > best) { best = v1; bq = 1; }
            if (v2 > best) { best = v2; bq = 2; }
            if (v3 > best) { best = v3; bq = 3; }
            float wb = best;
            #pragma unroll
            for (int off = 16; off > 0; off >>= 1) wb = fmaxf(wb, __shfl_xor_sync(0xffffffffu, wb, off));
            unsigned m = __ballot_sync(0xffffffffu, best == wb);
            int owner = __ffs(m) - 1;
            if (t == owner) {
                if (bq == 0) v0 = -3.0e38f;
                else if (bq == 1) v1 = -3.0e38f;
                else if (bq == 2) v2 = -3.0e38f;
                else v3 = -3.0e38f;
            }
            float l = wb * 10.0f;
            if (it == 0) { Lmax = l; S = 1.0f; }
            else S += __expf(l - Lmax);
        }
        float lp = p * 10.0f;
        if (lp > Lmax) { S = S * __expf(Lmax - lp) + 1.0f; Lmax = lp; }
        else S += __expf(lp - Lmax);
        float lossb = Lmax + logf(S) - lp;
        if (t == 0) atomicAdd(&g_loss, lossb);
    }
}

__global__ void k_final(float* out) {
    out[0] = g_loss * (1.0f / (float)BATCHB);
}

// ---------------- launch ----------------
extern "C" void kernel_launch(void* const* d_in, const int* in_sizes, int n_in,
                              void* d_out, int out_size) {
    const float* raw_item_embs = (const float*)d_in[0];
    const float* user_sem_base = (const float*)d_in[1];
    const float* sem_w         = (const float*)d_in[2];
    const float* sem_b         = (const float*)d_in[3];
    const float* collab_user_w = (const float*)d_in[4];
    const float* collab_item_w = (const float*)d_in[5];
    const float* adj_vals      = (const float*)d_in[6];
    const int*   adj_rows      = (const int*)d_in[7];
    const int*   adj_cols      = (const int*)d_in[8];
    const int*   uids          = (const int*)d_in[9];
    const int*   pos_iids      = (const int*)d_in[10];
    const int*   cand_ids      = (const int*)d_in[11];
    float* out = (float*)d_out;

    cudaFuncSetAttribute(k_sem_mma<false>, cudaFuncAttributeMaxDynamicSharedMemorySize, SM_BYTES);
    cudaFuncSetAttribute(k_sem_mma<true>,  cudaFuncAttributeMaxDynamicSharedMemorySize, SM_BYTES);

    cudaStream_t s2;
    cudaStreamCreateWithFlags(&s2, cudaStreamNonBlocking);
    cudaEvent_t evFork, evMark, evJoin;
    cudaEventCreateWithFlags(&evFork, cudaEventDisableTiming);
    cudaEventCreateWithFlags(&evMark, cudaEventDisableTiming);
    cudaEventCreateWithFlags(&evJoin, cudaEventDisableTiming);

    cudaEventRecord(evFork, 0);
    cudaStreamWaitEvent(s2, evFork, 0);

    // side stream: umark/loss zero + mark, then independent sem GEMMs
    k_zu<<<(UMARK_WORDS + 255) / 256, 256, 0, s2>>>();
    k_mark<<<(BATCHB + 255) / 256, 256, 0, s2>>>(uids);
    cudaEventRecord(evMark, s2);
    k_sem_mma<false><<<(N_ITEMS + 127) / 128, 256, SM_BYTES, s2>>>(raw_item_embs, sem_w, sem_b,
                                                                   nullptr, N_ITEMS);
    k_sem_mma<true><<<BATCHB / 128, 256, SM_BYTES, s2>>>(user_sem_base, sem_w, sem_b,
                                                         uids, BATCHB);
    cudaEventRecord(evJoin, s2);

    // main chain: ego fp16 conversion + CSR build + GCN
    k_conv<<<(N_TOT * 32 + 255) / 256, 256>>>(collab_user_w, collab_item_w);
    k_zero<<<(N_TOT + 255) / 256, 256>>>();
    k_hist<<<NE / 256, 256>>>(adj_rows);
    k_scan1<<<NB_SCAN, 256>>>();
    k_scan2<<<1, 256>>>();
    k_scan3<<<NB_SCAN, 256>>>();
    k_scatter<<<NE / 256, 256>>>(adj_rows, adj_cols, adj_vals);

    int spmm_blocks = (N_TOT * 16 + 255) / 256;
    k_spmm<0><<<spmm_blocks, 256>>>(collab_user_w, collab_item_w);
    k_spmm<1><<<spmm_blocks, 256>>>(collab_user_w, collab_item_w);
    cudaStreamWaitEvent(0, evMark, 0);
    k_spmm<2><<<spmm_blocks, 256>>>(collab_user_w, collab_item_w);

    k_collab_users<<<(BATCHB * 32 + 255) / 256, 256>>>(uids);

    cudaStreamWaitEvent(0, evJoin, 0);
    k_score<<<BATCHB, 128>>>(pos_iids, cand_ids);
    k_final<<<1, 1>>>(out);

    cudaEventDestroy(evFork);
    cudaEventDestroy(evMark);
    cudaEventDestroy(evJoin);
    cudaStreamDestroy(s2);
}

// round 11
// speedup vs baseline: 1.0677x; 1.0314x over previous
#include <cuda_runtime.h>
#include <cuda_bf16.h>
#include <cuda_fp16.h>
#include <math.h>
#include <stdint.h>

#define N_USERS 100000
#define N_ITEMS 50000
#define N_TOT   150000
#define IN_DIM  768
#define BR      64
#define NE      2097152
#define BATCHB  4096
#define NCAND   128
#define NNEG    16
#define DIM     128
#define INV_SQRT2 0.70710678118f
#define NB_SCAN 147
#define UMARK_WORDS ((N_USERS + 31) / 32)
#define M_GEMM (N_ITEMS + BATCHB)       /* unified GEMM rows */

// ---------------- scratch (device globals; NEVER referenced from host code) ----------------
__device__ __half2 g_l0h[(size_t)N_TOT * 32];
__device__ __half2 g_l1h[(size_t)N_TOT * 32];
__device__ __half2 g_l2h[(size_t)N_TOT * 32];
__device__ float g_acc  [(size_t)N_TOT * BR];
__device__ float g_i_all[(size_t)N_ITEMS * DIM];
__device__ float g_batch_u[(size_t)BATCHB * DIM];
__device__ uint16_t g_wh[IN_DIM * BR];
__device__ uint16_t g_wl[IN_DIM * BR];
__device__ int   g_row_ptr[N_TOT + 1];
__device__ int   g_row_cnt[N_TOT];
__device__ int   g_rank[NE];
__device__ int2  g_cv[NE];
__device__ int   g_bsum[256];
__device__ unsigned g_umark[UMARK_WORDS];
__device__ float g_loss;

// ---------------- zeroing / marking / conversions ----------------
__global__ void k_zero() {
    int i = blockIdx.x * blockDim.x + threadIdx.x;
    if (i < N_TOT) g_row_cnt[i] = 0;
}

__global__ void k_zu() {
    int i = blockIdx.x * blockDim.x + threadIdx.x;
    if (i < UMARK_WORDS) g_umark[i] = 0u;
    if (i == 0) g_loss = 0.0f;
}

__global__ void k_mark(const int* __restrict__ uids) {
    int i = blockIdx.x * blockDim.x + threadIdx.x;
    if (i < BATCHB) {
        int u = uids[i];
        atomicOr(&g_umark[u >> 5], 1u << (u & 31));
    }
}

__global__ void k_conv(const float* __restrict__ uw, const float* __restrict__ iw) {
    int i = blockIdx.x * blockDim.x + threadIdx.x;
    if (i >= N_TOT * 32) return;
    int idx2 = i * 2;
    int row = idx2 >> 6, c = idx2 & 63;
    const float* src = (row < N_USERS) ? uw + (size_t)row * BR
                                       : iw + (size_t)(row - N_USERS) * BR;
    float2 v = *(const float2*)(src + c);
    g_l0h[i] = __floats2half2_rn(v.x, v.y);
}

// W hi/lo bf16 split, computed once (saves ~57M per-CTA ALU ops in the GEMM)
__global__ void k_wsplit(const float* __restrict__ W) {
    int i = blockIdx.x * blockDim.x + threadIdx.x;
    if (i >= IN_DIM * BR) return;
    float wv = W[i];
    uint32_t wi = __float_as_uint(wv);
    float lo = wv - __uint_as_float(wi & 0xFFFF0000u);
    __nv_bfloat16 bl = __float2bfloat16(lo);
    g_wh[i] = (uint16_t)(wi >> 16);
    g_wl[i] = *(uint16_t*)&bl;
}

// ---------------- CSR build ----------------
__global__ void k_hist(const int* __restrict__ rows) {
    int i = blockIdx.x * blockDim.x + threadIdx.x;
    if (i < NE) g_rank[i] = atomicAdd(&g_row_cnt[rows[i]], 1);
}

__global__ void k_scan1() {
    __shared__ int red[256];
    int b = blockIdx.x, t = threadIdx.x;
    int base = b * 1024 + t * 4;
    int s = 0;
    #pragma unroll
    for (int q = 0; q < 4; q++) { int i = base + q; if (i < N_TOT) s += g_row_cnt[i]; }
    red[t] = s; __syncthreads();
    for (int off = 128; off > 0; off >>= 1) {
        if (t < off) red[t] += red[t + off];
        __syncthreads();
    }
    if (t == 0) g_bsum[b] = red[0];
}

__global__ void k_scan2() {
    __shared__ int sh[256];
    int t = threadIdx.x;
    int v = (t < NB_SCAN) ? g_bsum[t] : 0;
    sh[t] = v; __syncthreads();
    for (int off = 1; off < 256; off <<= 1) {
        int x = (t >= off) ? sh[t - off] : 0;
        __syncthreads();
        sh[t] += x;
        __syncthreads();
    }
    if (t < NB_SCAN) g_bsum[t] = sh[t] - v;
}

__global__ void k_scan3() {
    __shared__ int tsum[256];
    int b = blockIdx.x, t = threadIdx.x;
    int base = b * 1024 + t * 4;
    int c0 = 0, c1 = 0, c2 = 0, c3 = 0;
    if (base + 0 < N_TOT) c0 = g_row_cnt[base + 0];
    if (base + 1 < N_TOT) c1 = g_row_cnt[base + 1];
    if (base + 2 < N_TOT) c2 = g_row_cnt[base + 2];
    if (base + 3 < N_TOT) c3 = g_row_cnt[base + 3];
    int p1 = c0, p2 = c0 + c1, p3 = c0 + c1 + c2, s = p3 + c3;
    tsum[t] = s; __syncthreads();
    for (int off = 1; off < 256; off <<= 1) {
        int v = (t >= off) ? tsum[t - off] : 0;
        __syncthreads();
        tsum[t] += v;
        __syncthreads();
    }
    int excl = tsum[t] - s + g_bsum[b];
    if (base + 0 < N_TOT) g_row_ptr[base + 0] = excl;
    if (base + 1 < N_TOT) g_row_ptr[base + 1] = excl + p1;
    if (base + 2 < N_TOT) g_row_ptr[base + 2] = excl + p2;
    if (base + 3 < N_TOT) g_row_ptr[base + 3] = excl + p3;
    if (b == 0 && t == 0) g_row_ptr[N_TOT] = NE;
}

__global__ void k_scatter(const int* __restrict__ rows, const int* __restrict__ cols,
                          const float* __restrict__ vals) {
    int i = blockIdx.x * blockDim.x + threadIdx.x;
    if (i >= NE) return;
    int r = rows[i];
    g_cv[g_row_ptr[r] + g_rank[i]] = make_int2(cols[i], __float_as_int(vals[i]));
}

// ---------------- SpMM: half-warp per row, fp16 gathers, 8-wide load batching ----------------
template<int MODE>
__global__ void __launch_bounds__(128) k_spmm(const float* __restrict__ uw,
                                              const float* __restrict__ iw) {
    int tid = blockIdx.x * blockDim.x + threadIdx.x;
    int w = tid >> 4;
    int l = threadIdx.x & 15;
    int half16 = threadIdx.x & 16;

    bool valid = (w < N_TOT);
    if (MODE == 2 && valid && w < N_USERS && !((g_umark[w >> 5] >> (w & 31)) & 1u))
        valid = false;

    int s = 0, e = 0;
    if (valid) { s = g_row_ptr[w]; e = g_row_ptr[w + 1]; }
    int len = e - s;
    int olen = __shfl_xor_sync(0xffffffffu, len, 16);
    int maxlen = max(len, olen);

    const __half2* __restrict__ in = (MODE == 0) ? g_l0h : (MODE == 1) ? g_l1h : g_l2h;

    float a0 = 0.0f, a1 = 0.0f, a2 = 0.0f, a3 = 0.0f;

    for (int base = 0; base < maxlen; base += 16) {
        int idx = s + base + l;
        int c = 0; float v = 0.0f;
        if (idx < e) { int2 cv = __ldg(&g_cv[idx]); c = cv.x; v = __int_as_float(cv.y); }
        int cnt = len - base; cnt = min(16, max(cnt, 0));
        int ocnt = __shfl_xor_sync(0xffffffffu, cnt, 16);
        int m8 = (max(cnt, ocnt) + 7) & ~7;
        for (int j = 0; j < m8; j += 8) {
            int cc[8]; float vv[8];
            #pragma unroll
            for (int q = 0; q < 8; q++) {
                cc[q] = __shfl_sync(0xffffffffu, c, half16 + j + q);
                vv[q] = __shfl_sync(0xffffffffu, v, half16 + j + q);
            }
            uint2 qv[8];
            #pragma unroll
            for (int q = 0; q < 8; q++)
                qv[q] = __ldg((const uint2*)(in + (size_t)cc[q] * 32) + l);
            #pragma unroll
            for (int q = 0; q < 8; q++) {
                float2 f0 = __half22float2(*(__half2*)&qv[q].x);
                float2 f1 = __half22float2(*(__half2*)&qv[q].y);
                a0 = fmaf(vv[q], f0.x, a0); a1 = fmaf(vv[q], f0.y, a1);
                a2 = fmaf(vv[q], f1.x, a2); a3 = fmaf(vv[q], f1.y, a3);
            }
        }
    }

    if (MODE == 2) {
        float t0 = 0, t1 = 0, t2 = 0, t3 = 0;
        if (valid) {
            const float* rp = (w < N_USERS) ? uw + (size_t)w * BR
                                            : iw + (size_t)(w - N_USERS) * BR;
            float4 r = __ldg((const float4*)rp + l);
            uint2 q1 = *((const uint2*)(g_l1h + (size_t)w * 32) + l);
            uint2 q2 = *((const uint2*)(g_l2h + (size_t)w * 32) + l);
            float2 x1a = __half22float2(*(__half2*)&q1.x);
            float2 x1b = __half22float2(*(__half2*)&q1.y);
            float2 x2a = __half22float2(*(__half2*)&q2.x);
            float2 x2b = __half22float2(*(__half2*)&q2.y);
            t0 = r.x + x1a.x + x2a.x + a0;
            t1 = r.y + x1a.y + x2a.y + a1;
            t2 = r.z + x1b.x + x2b.x + a2;
            t3 = r.w + x1b.y + x2b.y + a3;
        }
        float ss = t0 * t0 + t1 * t1 + t2 * t2 + t3 * t3;
        #pragma unroll
        for (int off = 8; off > 0; off >>= 1)
            ss += __shfl_xor_sync(0xffffffffu, ss, off);
        if (valid) {
            if (w < N_USERS) {
                *((float4*)(g_acc + (size_t)w * BR) + l) = make_float4(t0, t1, t2, t3);
            } else {
                float sc = INV_SQRT2 / fmaxf(sqrtf(ss), 1e-12f);
                float* op = g_i_all + (size_t)(w - N_USERS) * DIM;
                *((float4*)op + l) = make_float4(t0 * sc, t1 * sc, t2 * sc, t3 * sc);
            }
        }
    } else if (valid) {
        __half2* op = (MODE == 0) ? g_l1h : g_l2h;
        __half2 ha = __floats2half2_rn(a0, a1);
        __half2 hb = __floats2half2_rn(a2, a3);
        uint2 q;
        q.x = *(uint32_t*)&ha;
        q.y = *(uint32_t*)&hb;
        *((uint2*)(op + (size_t)w * 32) + l) = q;
    }
}

__global__ void k_collab_users(const int* __restrict__ uids) {
    int w = (blockIdx.x * blockDim.x + threadIdx.x) >> 5;
    int lane = threadIdx.x & 31;
    if (w >= BATCHB) return;
    int u = uids[w];
    size_t o = (size_t)u * BR;
    float v0 = g_acc[o + lane], v1 = g_acc[o + lane + 32];
    float ss = v0 * v0 + v1 * v1;
    #pragma unroll
    for (int off = 16; off > 0; off >>= 1) ss += __shfl_xor_sync(0xffffffffu, ss, off);
    float sc = INV_SQRT2 / fmaxf(sqrtf(ss), 1e-12f);
    g_batch_u[(size_t)w * DIM + lane] = v0 * sc;
    g_batch_u[(size_t)w * DIM + lane + 32] = v1 * sc;
}

// ---------------- unified split-bf16 mma.sync semantic GEMM ----------------
// Rows [0, N_ITEMS) = items (direct), rows [N_ITEMS, M_GEMM) = users (gathered via uids).
#define KC 64
#define KP 72
#define NCHUNKS (IN_DIM / KC)
#define SA_H 0
#define SA_L (128 * KP)
#define SB_H (2 * 128 * KP)
#define SB_L (2 * 128 * KP + 64 * KP)
#define SM_U16_TOTAL (2 * 128 * KP + 2 * 64 * KP)
#define SM_BYTES (SM_U16_TOTAL * 2)

__device__ __forceinline__ void mma_bf16(float* d, uint32_t a0, uint32_t a1, uint32_t a2,
                                         uint32_t a3, uint32_t b0, uint32_t b1) {
    asm volatile("mma.sync.aligned.m16n8k16.row.col.f32.bf16.bf16.f32 "
                 "{%0,%1,%2,%3}, {%4,%5,%6,%7}, {%8,%9}, {%0,%1,%2,%3};"
                 : "+f"(d[0]), "+f"(d[1]), "+f"(d[2]), "+f"(d[3])
                 : "r"(a0), "r"(a1), "r"(a2), "r"(a3), "r"(b0), "r"(b1));
}

__device__ __forceinline__ void split2(float x, float y, uint32_t& hi, uint32_t& lo) {
    uint32_t xi = __float_as_uint(x), yi = __float_as_uint(y);
    hi = __byte_perm(xi, yi, 0x7632);
    float lx = x - __uint_as_float(xi & 0xFFFF0000u);
    float ly = y - __uint_as_float(yi & 0xFFFF0000u);
    __nv_bfloat162 p = __floats2bfloat162_rn(lx, ly);
    lo = *(uint32_t*)&p;
}

__global__ void __launch_bounds__(256) k_sem_mma(const float* __restrict__ Ai,
                                                 const float* __restrict__ Au,
                                                 const float* __restrict__ bias,
                                                 const int* __restrict__ gidx) {
    extern __shared__ uint16_t sm[];
    int t = threadIdx.x, wid = t >> 5, lane = t & 31;
    int rowbase = blockIdx.x * 128;

    int ar = t >> 1, kh = (t & 1) * 32;
    int grow = rowbase + ar;
    bool av = grow < M_GEMM;
    const float* arp;
    if (!av) arp = Ai;                                  // dummy
    else if (grow < N_ITEMS) arp = Ai + (size_t)grow * IN_DIM;
    else arp = Au + (size_t)__ldg(gidx + (grow - N_ITEMS)) * IN_DIM;

    int bn = t & 63, bk0 = t >> 6;

    float acc[8][4];
    #pragma unroll
    for (int i = 0; i < 8; i++)
        #pragma unroll
        for (int j = 0; j < 4; j++) acc[i][j] = 0.0f;

    int mr = wid * 16;
    int r0 = mr + (lane >> 2);
    int kq0 = (lane & 3) * 2;

    for (int ch = 0; ch < NCHUNKS; ch++) {
        int k0 = ch * KC;
        __syncthreads();
        #pragma unroll
        for (int i = 0; i < 8; i++) {
            int k = kh + i * 4;
            float4 a = av ? __ldg((const float4*)(arp + k0 + k)) : make_float4(0, 0, 0, 0);
            uint32_t h01, l01, h23, l23;
            split2(a.x, a.y, h01, l01);
            split2(a.z, a.w, h23, l23);
            int o = ar * KP + k;
            *(uint32_t*)(sm + SA_H + o)     = h01;
            *(uint32_t*)(sm + SA_H + o + 2) = h23;
            *(uint32_t*)(sm + SA_L + o)     = l01;
            *(uint32_t*)(sm + SA_L + o + 2) = l23;
        }
        // B staging: precomputed splits, plain loads
        #pragma unroll
        for (int i = 0; i < 16; i++) {
            int k = bk0 + i * 4;
            int gsrc = (k0 + k) * BR + bn;
            int o = bn * KP + k;
            sm[SB_H + o] = g_wh[gsrc];
            sm[SB_L + o] = g_wl[gsrc];
        }
        __syncthreads();
        #pragma unroll
        for (int ks = 0; ks < 4; ks++) {
            int kq = ks * 16 + kq0;
            const uint16_t* pah = sm + SA_H + kq;
            const uint16_t* pal = sm + SA_L + kq;
            uint32_t ah0 = *(const uint32_t*)(pah + r0 * KP);
            uint32_t ah1 = *(const uint32_t*)(pah + (r0 + 8) * KP);
            uint32_t ah2 = *(const uint32_t*)(pah + r0 * KP + 8);
            uint32_t ah3 = *(const uint32_t*)(pah + (r0 + 8) * KP + 8);
            uint32_t al0 = *(const uint32_t*)(pal + r0 * KP);
            uint32_t al1 = *(const uint32_t*)(pal + (r0 + 8) * KP);
            uint32_t al2 = *(const uint32_t*)(pal + r0 * KP + 8);
            uint32_t al3 = *(const uint32_t*)(pal + (r0 + 8) * KP + 8);
            #pragma unroll
            for (int nt = 0; nt < 8; nt++) {
                int n = nt * 8 + (lane >> 2);
                uint32_t bh0 = *(const uint32_t*)(sm + SB_H + n * KP + kq);
                uint32_t bh1 = *(const uint32_t*)(sm + SB_H + n * KP + kq + 8);
                uint32_t bl0 = *(const uint32_t*)(sm + SB_L + n * KP + kq);
                uint32_t bl1 = *(const uint32_t*)(sm + SB_L + n * KP + kq + 8);
                mma_bf16(acc[nt], ah0, ah1, ah2, ah3, bh0, bh1);
                mma_bf16(acc[nt], ah0, ah1, ah2, ah3, bl0, bl1);
                mma_bf16(acc[nt], al0, al1, al2, al3, bh0, bh1);
            }
        }
    }

    float ss0 = 0.0f, ss1 = 0.0f;
    #pragma unroll
    for (int nt = 0; nt < 8; nt++) {
        int c = nt * 8 + (lane & 3) * 2;
        float b0 = __ldg(bias + c), b1 = __ldg(bias + c + 1);
        acc[nt][0] += b0; acc[nt][1] += b1;
        acc[nt][2] += b0; acc[nt][3] += b1;
        ss0 += acc[nt][0] * acc[nt][0] + acc[nt][1] * acc[nt][1];
        ss1 += acc[nt][2] * acc[nt][2] + acc[nt][3] * acc[nt][3];
    }
    ss0 += __shfl_xor_sync(0xffffffffu, ss0, 1);
    ss0 += __shfl_xor_sync(0xffffffffu, ss0, 2);
    ss1 += __shfl_xor_sync(0xffffffffu, ss1, 1);
    ss1 += __shfl_xor_sync(0xffffffffu, ss1, 2);
    float sc0 = INV_SQRT2 / fmaxf(sqrtf(ss0), 1e-12f);
    float sc1 = INV_SQRT2 / fmaxf(sqrtf(ss1), 1e-12f);
    int gr0 = rowbase + r0, gr1 = gr0 + 8;
    #pragma unroll
    for (int nt = 0; nt < 8; nt++) {
        int c = nt * 8 + (lane & 3) * 2;
        if (gr0 < M_GEMM) {
            float* op = (gr0 < N_ITEMS) ? g_i_all + (size_t)gr0 * DIM
                                        : g_batch_u + (size_t)(gr0 - N_ITEMS) * DIM;
            *(float2*)(op + BR + c) = make_float2(acc[nt][0] * sc0, acc[nt][1] * sc0);
        }
        if (gr1 < M_GEMM) {
            float* op = (gr1 < N_ITEMS) ? g_i_all + (size_t)gr1 * DIM
                                        : g_batch_u + (size_t)(gr1 - N_ITEMS) * DIM;
            *(float2*)(op + BR + c) = make_float2(acc[nt][2] * sc1, acc[nt][3] * sc1);
        }
    }
}

// ---------------- scoring: block per batch row ----------------
__global__ void k_score(const int* __restrict__ pos_iids, const int* __restrict__ cand_ids) {
    __shared__ __align__(16) float su[128];
    __shared__ float sc[128];
    int b = blockIdx.x, t = threadIdx.x;
    su[t] = g_batch_u[(size_t)b * DIM + t];
    __syncthreads();
    int pos = pos_iids[b];
    int id = cand_ids[(size_t)b * NCAND + t];
    if (id == pos) id = (id + 1) % N_ITEMS;
    const float4* ip = (const float4*)(g_i_all + (size_t)id * DIM);
    const float4* us = (const float4*)su;
    float a = 0.0f;
    #pragma unroll
    for (int j = 0; j < 32; j++) {
        float4 iv = __ldg(ip + j);
        float4 uv = us[j];
        a += iv.x * uv.x + iv.y * uv.y + iv.z * uv.z + iv.w * uv.w;
    }
    sc[t] = a;
    __syncthreads();

    if (t < 32) {
        const float* pp = g_i_all + (size_t)pos * DIM;
        float p = pp[t] * su[t] + pp[t + 32] * su[t + 32] +
                  pp[t + 64] * su[t + 64] + pp[t + 96] * su[t + 96];
        #pragma unroll
        for (int off = 16; off > 0; off >>= 1) p += __shfl_xor_sync(0xffffffffu, p, off);

        float v0 = sc[t * 4], v1 = sc[t * 4 + 1], v2 = sc[t * 4 + 2], v3 = sc[t * 4 + 3];
        float Lmax = 0.0f, S = 0.0f;
        for (int it = 0; it < NNEG; it++) {
            float best = v0; int bq = 0;
            if (v1 > best) { best = v1; bq = 1; }
            if (v2 > best) { best = v2; bq = 2; }
            if (v3 > best) { best = v3; bq = 3; }
            float wb = best;
            #pragma unroll
            for (int off = 16; off > 0; off >>= 1) wb = fmaxf(wb, __shfl_xor_sync(0xffffffffu, wb, off));
            unsigned m = __ballot_sync(0xffffffffu, best == wb);
            int owner = __ffs(m) - 1;
            if (t == owner) {
                if (bq == 0) v0 = -3.0e38f;
                else if (bq == 1) v1 = -3.0e38f;
                else if (bq == 2) v2 = -3.0e38f;
                else v3 = -3.0e38f;
            }
            float l = wb * 10.0f;
            if (it == 0) { Lmax = l; S = 1.0f; }
            else S += __expf(l - Lmax);
        }
        float lp = p * 10.0f;
        if (lp > Lmax) { S = S * __expf(Lmax - lp) + 1.0f; Lmax = lp; }
        else S += __expf(lp - Lmax);
        float lossb = Lmax + logf(S) - lp;
        if (t == 0) atomicAdd(&g_loss, lossb);
    }
}

__global__ void k_final(float* out) {
    out[0] = g_loss * (1.0f / (float)BATCHB);
}

// ---------------- launch ----------------
extern "C" void kernel_launch(void* const* d_in, const int* in_sizes, int n_in,
                              void* d_out, int out_size) {
    const float* raw_item_embs = (const float*)d_in[0];
    const float* user_sem_base = (const float*)d_in[1];
    const float* sem_w         = (const float*)d_in[2];
    const float* sem_b         = (const float*)d_in[3];
    const float* collab_user_w = (const float*)d_in[4];
    const float* collab_item_w = (const float*)d_in[5];
    const float* adj_vals      = (const float*)d_in[6];
    const int*   adj_rows      = (const int*)d_in[7];
    const int*   adj_cols      = (const int*)d_in[8];
    const int*   uids          = (const int*)d_in[9];
    const int*   pos_iids      = (const int*)d_in[10];
    const int*   cand_ids      = (const int*)d_in[11];
    float* out = (float*)d_out;

    cudaFuncSetAttribute(k_sem_mma, cudaFuncAttributeMaxDynamicSharedMemorySize, SM_BYTES);

    cudaStream_t s2;
    cudaStreamCreateWithFlags(&s2, cudaStreamNonBlocking);
    cudaEvent_t evFork, evMark, evConv, evJoin;
    cudaEventCreateWithFlags(&evFork, cudaEventDisableTiming);
    cudaEventCreateWithFlags(&evMark, cudaEventDisableTiming);
    cudaEventCreateWithFlags(&evConv, cudaEventDisableTiming);
    cudaEventCreateWithFlags(&evJoin, cudaEventDisableTiming);

    cudaEventRecord(evFork, 0);
    cudaStreamWaitEvent(s2, evFork, 0);

    // side stream: small setup + ego conversion + unified sem GEMM
    k_zu<<<(UMARK_WORDS + 255) / 256, 256, 0, s2>>>();
    k_mark<<<(BATCHB + 255) / 256, 256, 0, s2>>>(uids);
    cudaEventRecord(evMark, s2);
    k_conv<<<(N_TOT * 32 + 255) / 256, 256, 0, s2>>>(collab_user_w, collab_item_w);
    cudaEventRecord(evConv, s2);
    k_wsplit<<<(IN_DIM * BR + 255) / 256, 256, 0, s2>>>(sem_w);
    k_sem_mma<<<(M_GEMM + 127) / 128, 256, SM_BYTES, s2>>>(raw_item_embs, user_sem_base,
                                                           sem_b, uids);
    cudaEventRecord(evJoin, s2);

    // main chain: CSR build + GCN
    k_zero<<<(N_TOT + 255) / 256, 256>>>();
    k_hist<<<NE / 256, 256>>>(adj_rows);
    k_scan1<<<NB_SCAN, 256>>>();
    k_scan2<<<1, 256>>>();
    k_scan3<<<NB_SCAN, 256>>>();
    k_scatter<<<NE / 256, 256>>>(adj_rows, adj_cols, adj_vals);

    int spmm_blocks = (N_TOT * 16 + 127) / 128;
    cudaStreamWaitEvent(0, evConv, 0);   // spmm<0> reads g_l0h
    k_spmm<0><<<spmm_blocks, 128>>>(collab_user_w, collab_item_w);
    k_spmm<1><<<spmm_blocks, 128>>>(collab_user_w, collab_item_w);
    cudaStreamWaitEvent(0, evMark, 0);   // spmm<2> reads g_umark
    k_spmm<2><<<spmm_blocks, 128>>>(collab_user_w, collab_item_w);

    k_collab_users<<<(BATCHB * 32 + 255) / 256, 256>>>(uids);

    cudaStreamWaitEvent(0, evJoin, 0);   // score needs sem halves + g_loss zeroed
    k_score<<<BATCHB, 128>>>(pos_iids, cand_ids);
    k_final<<<1, 1>>>(out);

    cudaEventDestroy(evFork);
    cudaEventDestroy(evMark);
    cudaEventDestroy(evConv);
    cudaEventDestroy(evJoin);
    cudaStreamDestroy(s2);
}

// round 16
// speedup vs baseline: 1.1273x; 1.0558x over previous
#include <cuda_runtime.h>
#include <cuda_bf16.h>
#include <cuda_fp16.h>
#include <math.h>
#include <stdint.h>

#define N_USERS 100000
#define N_ITEMS 50000
#define N_TOT   150000
#define IN_DIM  768
#define BR      64
#define NE      2097152
#define BATCHB  4096
#define NCAND   128
#define NNEG    16
#define DIM     128
#define INV_SQRT2 0.70710678118f
#define NB_SCAN 147
#define UMARK_WORDS ((N_USERS + 31) / 32)
#define M_GEMM (N_ITEMS + BATCHB)

// ---------------- scratch (device globals; NEVER referenced from host code) ----------------
__device__ __half2 g_l0h[(size_t)N_TOT * 32];
__device__ __half2 g_l1h[(size_t)N_TOT * 32];
__device__ __half2 g_l2h[(size_t)N_TOT * 32];
__device__ float   g_acc[(size_t)N_TOT * BR];     // marked-user rows only
__device__ __half2 g_i_h [(size_t)N_ITEMS * 64];  // item embeddings (128 cols, fp16)
__device__ __half2 g_bu_h[(size_t)BATCHB * 64];   // batch user embeddings (fp16)
__device__ uint16_t g_wh[IN_DIM * BR];
__device__ uint16_t g_wl[IN_DIM * BR];
__device__ int   g_row_ptr[N_TOT + 1];
__device__ int   g_row_cnt[N_TOT];
__device__ int   g_rank[NE];
__device__ int2  g_cv[NE];
__device__ int   g_bsum[256];
__device__ unsigned g_umark[UMARK_WORDS];
__device__ float g_loss;

// ---------------- zeroing / marking / conversions ----------------
__global__ void k_zero() {
    int i = blockIdx.x * blockDim.x + threadIdx.x;
    if (i < N_TOT) g_row_cnt[i] = 0;
}

__global__ void k_zu() {
    int i = blockIdx.x * blockDim.x + threadIdx.x;
    if (i < UMARK_WORDS) g_umark[i] = 0u;
    if (i == 0) g_loss = 0.0f;
}

__global__ void k_mark(const int* __restrict__ uids) {
    int i = blockIdx.x * blockDim.x + threadIdx.x;
    if (i < BATCHB) {
        int u = uids[i];
        atomicOr(&g_umark[u >> 5], 1u << (u & 31));
    }
}

__global__ void k_conv(const float* __restrict__ uw, const float* __restrict__ iw) {
    int i = blockIdx.x * blockDim.x + threadIdx.x;
    if (i >= N_TOT * 32) return;
    int idx2 = i * 2;
    int row = idx2 >> 6, c = idx2 & 63;
    const float* src = (row < N_USERS) ? uw + (size_t)row * BR
                                       : iw + (size_t)(row - N_USERS) * BR;
    float2 v = __ldcs((const float2*)(src + c));
    g_l0h[i] = __floats2half2_rn(v.x, v.y);
}

__global__ void k_wsplit(const float* __restrict__ W) {
    int i = blockIdx.x * blockDim.x + threadIdx.x;
    if (i >= IN_DIM * BR) return;
    float wv = W[i];
    uint32_t wi = __float_as_uint(wv);
    float lo = wv - __uint_as_float(wi & 0xFFFF0000u);
    __nv_bfloat16 bl = __float2bfloat16(lo);
    g_wh[i] = (uint16_t)(wi >> 16);
    g_wl[i] = *(uint16_t*)&bl;
}

// ---------------- CSR build ----------------
__global__ void k_hist(const int* __restrict__ rows) {
    int i = blockIdx.x * blockDim.x + threadIdx.x;
    if (i < NE) g_rank[i] = atomicAdd(&g_row_cnt[__ldcs(rows + i)], 1);
}

__global__ void k_scan1() {
    __shared__ int red[256];
    int b = blockIdx.x, t = threadIdx.x;
    int base = b * 1024 + t * 4;
    int s = 0;
    #pragma unroll
    for (int q = 0; q < 4; q++) { int i = base + q; if (i < N_TOT) s += g_row_cnt[i]; }
    red[t] = s; __syncthreads();
    for (int off = 128; off > 0; off >>= 1) {
        if (t < off) red[t] += red[t + off];
        __syncthreads();
    }
    if (t == 0) g_bsum[b] = red[0];
}

__global__ void k_scan2() {
    __shared__ int sh[256];
    int t = threadIdx.x;
    int v = (t < NB_SCAN) ? g_bsum[t] : 0;
    sh[t] = v; __syncthreads();
    for (int off = 1; off < 256; off <<= 1) {
        int x = (t >= off) ? sh[t - off] : 0;
        __syncthreads();
        sh[t] += x;
        __syncthreads();
    }
    if (t < NB_SCAN) g_bsum[t] = sh[t] - v;
}

__global__ void k_scan3() {
    __shared__ int tsum[256];
    int b = blockIdx.x, t = threadIdx.x;
    int base = b * 1024 + t * 4;
    int c0 = 0, c1 = 0, c2 = 0, c3 = 0;
    if (base + 0 < N_TOT) c0 = g_row_cnt[base + 0];
    if (base + 1 < N_TOT) c1 = g_row_cnt[base + 1];
    if (base + 2 < N_TOT) c2 = g_row_cnt[base + 2];
    if (base + 3 < N_TOT) c3 = g_row_cnt[base + 3];
    int p1 = c0, p2 = c0 + c1, p3 = c0 + c1 + c2, s = p3 + c3;
    tsum[t] = s; __syncthreads();
    for (int off = 1; off < 256; off <<= 1) {
        int v = (t >= off) ? tsum[t - off] : 0;
        __syncthreads();
        tsum[t] += v;
        __syncthreads();
    }
    int excl = tsum[t] - s + g_bsum[b];
    if (base + 0 < N_TOT) g_row_ptr[base + 0] = excl;
    if (base + 1 < N_TOT) g_row_ptr[base + 1] = excl + p1;
    if (base + 2 < N_TOT) g_row_ptr[base + 2] = excl + p2;
    if (base + 3 < N_TOT) g_row_ptr[base + 3] = excl + p3;
    if (b == 0 && t == 0) g_row_ptr[N_TOT] = NE;
}

__global__ void k_scatter(const int* __restrict__ rows, const int* __restrict__ cols,
                          const float* __restrict__ vals) {
    int i = blockIdx.x * blockDim.x + threadIdx.x;
    if (i >= NE) return;
    int r = __ldcs(rows + i);
    int c = __ldcs(cols + i);
    float v = __ldcs(vals + i);
    g_cv[g_row_ptr[r] + g_rank[i]] = make_int2(c, __float_as_int(v));
}

// ---------------- SpMM: half-warp per row, fp16 gathers, 8-wide batching ----------------
template<int MODE>
__global__ void __launch_bounds__(128) k_spmm(const float* __restrict__ uw,
                                              const float* __restrict__ iw) {
    int tid = blockIdx.x * blockDim.x + threadIdx.x;
    int w = tid >> 4;
    int l = threadIdx.x & 15;
    int half16 = threadIdx.x & 16;

    bool valid = (w < N_TOT);
    if (MODE == 2 && valid && w < N_USERS && !((g_umark[w >> 5] >> (w & 31)) & 1u))
        valid = false;

    int s = 0, e = 0;
    if (valid) { s = g_row_ptr[w]; e = g_row_ptr[w + 1]; }
    int len = e - s;
    int olen = __shfl_xor_sync(0xffffffffu, len, 16);
    int maxlen = max(len, olen);

    const __half2* __restrict__ in = (MODE == 0) ? g_l0h : (MODE == 1) ? g_l1h : g_l2h;

    float a0 = 0.0f, a1 = 0.0f, a2 = 0.0f, a3 = 0.0f;

    for (int base = 0; base < maxlen; base += 16) {
        int idx = s + base + l;
        int c = 0; float v = 0.0f;
        if (idx < e) { int2 cv = __ldg(&g_cv[idx]); c = cv.x; v = __int_as_float(cv.y); }
        int cnt = len - base; cnt = min(16, max(cnt, 0));
        int ocnt = __shfl_xor_sync(0xffffffffu, cnt, 16);
        int m8 = (max(cnt, ocnt) + 7) & ~7;
        for (int j = 0; j < m8; j += 8) {
            int cc[8]; float vv[8];
            #pragma unroll
            for (int q = 0; q < 8; q++) {
                cc[q] = __shfl_sync(0xffffffffu, c, half16 + j + q);
                vv[q] = __shfl_sync(0xffffffffu, v, half16 + j + q);
            }
            uint2 qv[8];
            #pragma unroll
            for (int q = 0; q < 8; q++)
                qv[q] = __ldg((const uint2*)(in + (size_t)cc[q] * 32) + l);
            #pragma unroll
            for (int q = 0; q < 8; q++) {
                float2 f0 = __half22float2(*(__half2*)&qv[q].x);
                float2 f1 = __half22float2(*(__half2*)&qv[q].y);
                a0 = fmaf(vv[q], f0.x, a0); a1 = fmaf(vv[q], f0.y, a1);
                a2 = fmaf(vv[q], f1.x, a2); a3 = fmaf(vv[q], f1.y, a3);
            }
        }
    }

    if (MODE == 2) {
        float t0 = 0, t1 = 0, t2 = 0, t3 = 0;
        if (valid) {
            const float* rp = (w < N_USERS) ? uw + (size_t)w * BR
                                            : iw + (size_t)(w - N_USERS) * BR;
            float4 r = __ldcs((const float4*)rp + l);
            uint2 q1 = *((const uint2*)(g_l1h + (size_t)w * 32) + l);
            uint2 q2 = *((const uint2*)(g_l2h + (size_t)w * 32) + l);
            float2 x1a = __half22float2(*(__half2*)&q1.x);
            float2 x1b = __half22float2(*(__half2*)&q1.y);
            float2 x2a = __half22float2(*(__half2*)&q2.x);
            float2 x2b = __half22float2(*(__half2*)&q2.y);
            t0 = r.x + x1a.x + x2a.x + a0;
            t1 = r.y + x1a.y + x2a.y + a1;
            t2 = r.z + x1b.x + x2b.x + a2;
            t3 = r.w + x1b.y + x2b.y + a3;
        }
        float ss = t0 * t0 + t1 * t1 + t2 * t2 + t3 * t3;
        #pragma unroll
        for (int off = 8; off > 0; off >>= 1)
            ss += __shfl_xor_sync(0xffffffffu, ss, off);
        if (valid) {
            if (w < N_USERS) {
                *((float4*)(g_acc + (size_t)w * BR) + l) = make_float4(t0, t1, t2, t3);
            } else {
                float sc = INV_SQRT2 / fmaxf(sqrtf(ss), 1e-12f);
                __half2 h0 = __floats2half2_rn(t0 * sc, t1 * sc);
                __half2 h1 = __floats2half2_rn(t2 * sc, t3 * sc);
                uint2 q;
                q.x = *(uint32_t*)&h0;
                q.y = *(uint32_t*)&h1;
                *((uint2*)(g_i_h + (size_t)(w - N_USERS) * 64) + l) = q;
            }
        }
    } else if (valid) {
        __half2* op = (MODE == 0) ? g_l1h : g_l2h;
        __half2 ha = __floats2half2_rn(a0, a1);
        __half2 hb = __floats2half2_rn(a2, a3);
        uint2 q;
        q.x = *(uint32_t*)&ha;
        q.y = *(uint32_t*)&hb;
        *((uint2*)(op + (size_t)w * 32) + l) = q;
    }
}

__global__ void k_collab_users(const int* __restrict__ uids) {
    int w = (blockIdx.x * blockDim.x + threadIdx.x) >> 5;
    int lane = threadIdx.x & 31;
    if (w >= BATCHB) return;
    int u = uids[w];
    float2 v = *(const float2*)(g_acc + (size_t)u * BR + 2 * lane);
    float ss = v.x * v.x + v.y * v.y;
    #pragma unroll
    for (int off = 16; off > 0; off >>= 1) ss += __shfl_xor_sync(0xffffffffu, ss, off);
    float sc = INV_SQRT2 / fmaxf(sqrtf(ss), 1e-12f);
    g_bu_h[(size_t)w * 64 + lane] = __floats2half2_rn(v.x * sc, v.y * sc);
}

// ---------------- unified split-bf16 mma.sync semantic GEMM ----------------
#define KC 64
#define KP 72
#define NCHUNKS (IN_DIM / KC)
#define SA_H 0
#define SA_L (128 * KP)
#define SB_H (2 * 128 * KP)
#define SB_L (2 * 128 * KP + 64 * KP)
#define SM_U16_TOTAL (2 * 128 * KP + 2 * 64 * KP)
#define SM_BYTES (SM_U16_TOTAL * 2)

__device__ __forceinline__ void mma_bf16(float* d, uint32_t a0, uint32_t a1, uint32_t a2,
                                         uint32_t a3, uint32_t b0, uint32_t b1) {
    asm volatile("mma.sync.aligned.m16n8k16.row.col.f32.bf16.bf16.f32 "
                 "{%0,%1,%2,%3}, {%4,%5,%6,%7}, {%8,%9}, {%0,%1,%2,%3};"
                 : "+f"(d[0]), "+f"(d[1]), "+f"(d[2]), "+f"(d[3])
                 : "r"(a0), "r"(a1), "r"(a2), "r"(a3), "r"(b0), "r"(b1));
}

__device__ __forceinline__ void split2(float x, float y, uint32_t& hi, uint32_t& lo) {
    uint32_t xi = __float_as_uint(x), yi = __float_as_uint(y);
    hi = __byte_perm(xi, yi, 0x7632);
    float lx = x - __uint_as_float(xi & 0xFFFF0000u);
    float ly = y - __uint_as_float(yi & 0xFFFF0000u);
    __nv_bfloat162 p = __floats2bfloat162_rn(lx, ly);
    lo = *(uint32_t*)&p;
}

__global__ void __launch_bounds__(256) k_sem_mma(const float* __restrict__ Ai,
                                                 const float* __restrict__ Au,
                                                 const float* __restrict__ bias,
                                                 const int* __restrict__ gidx) {
    extern __shared__ uint16_t sm[];
    int t = threadIdx.x, wid = t >> 5, lane = t & 31;
    int rowbase = blockIdx.x * 128;

    int ar = t >> 1, kh = (t & 1) * 32;
    int grow = rowbase + ar;
    bool av = grow < M_GEMM;
    const float* arp;
    if (!av) arp = Ai;
    else if (grow < N_ITEMS) arp = Ai + (size_t)grow * IN_DIM;
    else arp = Au + (size_t)__ldg(gidx + (grow - N_ITEMS)) * IN_DIM;

    int bn = t & 63, bk0 = t >> 6;

    float acc[8][4];
    #pragma unroll
    for (int i = 0; i < 8; i++)
        #pragma unroll
        for (int j = 0; j < 4; j++) acc[i][j] = 0.0f;

    int mr = wid * 16;
    int r0 = mr + (lane >> 2);
    int kq0 = (lane & 3) * 2;

    for (int ch = 0; ch < NCHUNKS; ch++) {
        int k0 = ch * KC;
        __syncthreads();
        #pragma unroll
        for (int i = 0; i < 8; i++) {
            int k = kh + i * 4;
            float4 a = av ? __ldcs((const float4*)(arp + k0 + k)) : make_float4(0, 0, 0, 0);
            uint32_t h01, l01, h23, l23;
            split2(a.x, a.y, h01, l01);
            split2(a.z, a.w, h23, l23);
            int o = ar * KP + k;
            *(uint32_t*)(sm + SA_H + o)     = h01;
            *(uint32_t*)(sm + SA_H + o + 2) = h23;
            *(uint32_t*)(sm + SA_L + o)     = l01;
            *(uint32_t*)(sm + SA_L + o + 2) = l23;
        }
        #pragma unroll
        for (int i = 0; i < 16; i++) {
            int k = bk0 + i * 4;
            int gsrc = (k0 + k) * BR + bn;
            int o = bn * KP + k;
            sm[SB_H + o] = g_wh[gsrc];
            sm[SB_L + o] = g_wl[gsrc];
        }
        __syncthreads();
        #pragma unroll
        for (int ks = 0; ks < 4; ks++) {
            int kq = ks * 16 + kq0;
            const uint16_t* pah = sm + SA_H + kq;
            const uint16_t* pal = sm + SA_L + kq;
            uint32_t ah0 = *(const uint32_t*)(pah + r0 * KP);
            uint32_t ah1 = *(const uint32_t*)(pah + (r0 + 8) * KP);
            uint32_t ah2 = *(const uint32_t*)(pah + r0 * KP + 8);
            uint32_t ah3 = *(const uint32_t*)(pah + (r0 + 8) * KP + 8);
            uint32_t al0 = *(const uint32_t*)(pal + r0 * KP);
            uint32_t al1 = *(const uint32_t*)(pal + (r0 + 8) * KP);
            uint32_t al2 = *(const uint32_t*)(pal + r0 * KP + 8);
            uint32_t al3 = *(const uint32_t*)(pal + (r0 + 8) * KP + 8);
            #pragma unroll
            for (int nt = 0; nt < 8; nt++) {
                int n = nt * 8 + (lane >> 2);
                uint32_t bh0 = *(const uint32_t*)(sm + SB_H + n * KP + kq);
                uint32_t bh1 = *(const uint32_t*)(sm + SB_H + n * KP + kq + 8);
                uint32_t bl0 = *(const uint32_t*)(sm + SB_L + n * KP + kq);
                uint32_t bl1 = *(const uint32_t*)(sm + SB_L + n * KP + kq + 8);
                mma_bf16(acc[nt], ah0, ah1, ah2, ah3, bh0, bh1);
                mma_bf16(acc[nt], ah0, ah1, ah2, ah3, bl0, bl1);
                mma_bf16(acc[nt], al0, al1, al2, al3, bh0, bh1);
            }
        }
    }

    float ss0 = 0.0f, ss1 = 0.0f;
    #pragma unroll
    for (int nt = 0; nt < 8; nt++) {
        int c = nt * 8 + (lane & 3) * 2;
        float b0 = __ldg(bias + c), b1 = __ldg(bias + c + 1);
        acc[nt][0] += b0; acc[nt][1] += b1;
        acc[nt][2] += b0; acc[nt][3] += b1;
        ss0 += acc[nt][0] * acc[nt][0] + acc[nt][1] * acc[nt][1];
        ss1 += acc[nt][2] * acc[nt][2] + acc[nt][3] * acc[nt][3];
    }
    ss0 += __shfl_xor_sync(0xffffffffu, ss0, 1);
    ss0 += __shfl_xor_sync(0xffffffffu, ss0, 2);
    ss1 += __shfl_xor_sync(0xffffffffu, ss1, 1);
    ss1 += __shfl_xor_sync(0xffffffffu, ss1, 2);
    float sc0 = INV_SQRT2 / fmaxf(sqrtf(ss0), 1e-12f);
    float sc1 = INV_SQRT2 / fmaxf(sqrtf(ss1), 1e-12f);
    int gr0 = rowbase + r0, gr1 = gr0 + 8;
    #pragma unroll
    for (int nt = 0; nt < 8; nt++) {
        int c = nt * 8 + (lane & 3) * 2;
        if (gr0 < M_GEMM) {
            __half2* op = (gr0 < N_ITEMS) ? g_i_h + (size_t)gr0 * 64
                                          : g_bu_h + (size_t)(gr0 - N_ITEMS) * 64;
            op[32 + (c >> 1)] = __floats2half2_rn(acc[nt][0] * sc0, acc[nt][1] * sc0);
        }
        if (gr1 < M_GEMM) {
            __half2* op = (gr1 < N_ITEMS) ? g_i_h + (size_t)gr1 * 64
                                          : g_bu_h + (size_t)(gr1 - N_ITEMS) * 64;
            op[32 + (c >> 1)] = __floats2half2_rn(acc[nt][2] * sc1, acc[nt][3] * sc1);
        }
    }
}

// ---------------- scoring: block per batch row (fp16 embeddings, fp32 accum) ----------------
__global__ void k_score(const int* __restrict__ pos_iids, const int* __restrict__ cand_ids) {
    __shared__ float su[128];
    __shared__ float sc[128];
    int b = blockIdx.x, t = threadIdx.x;
    if (t < 64) {
        float2 f = __half22float2(g_bu_h[(size_t)b * 64 + t]);
        su[2 * t] = f.x; su[2 * t + 1] = f.y;
    }
    __syncthreads();
    int pos = pos_iids[b];
    int id = cand_ids[(size_t)b * NCAND + t];
    if (id == pos) id = (id + 1) % N_ITEMS;
    const uint4* ip = (const uint4*)(g_i_h + (size_t)id * 64);
    float a = 0.0f;
    #pragma unroll
    for (int j = 0; j < 16; j++) {
        uint4 q = __ldg(ip + j);
        float2 f0 = __half22float2(*(__half2*)&q.x);
        float2 f1 = __half22float2(*(__half2*)&q.y);
        float2 f2 = __half22float2(*(__half2*)&q.z);
        float2 f3 = __half22float2(*(__half2*)&q.w);
        const float* sp = su + j * 8;
        a += f0.x * sp[0] + f0.y * sp[1] + f1.x * sp[2] + f1.y * sp[3]
           + f2.x * sp[4] + f2.y * sp[5] + f3.x * sp[6] + f3.y * sp[7];
    }
    sc[t] = a;
    __syncthreads();

    if (t < 32) {
        float2 p0 = __half22float2(g_i_h[(size_t)pos * 64 + t]);
        float2 p1 = __half22float2(g_i_h[(size_t)pos * 64 + 32 + t]);
        float p = p0.x * su[2 * t] + p0.y * su[2 * t + 1]
                + p1.x * su[64 + 2 * t] + p1.y * su[64 + 2 * t + 1];
        #pragma unroll
        for (int off = 16; off > 0; off >>= 1) p += __shfl_xor_sync(0xffffffffu, p, off);

        float v0 = sc[t * 4], v1 = sc[t * 4 + 1], v2 = sc[t * 4 + 2], v3 = sc[t * 4 + 3];
        float Lmax = 0.0f, S = 0.0f;
        for (int it = 0; it < NNEG; it++) {
            float best = v0; int bq = 0;
            if (v1 > best) { best = v1; bq = 1; }
            if (v2 > best) { best = v2; bq = 2; }
            if (v3 > best) { best = v3; bq = 3; }
            float wb = best;
            #pragma unroll
            for (int off = 16; off > 0; off >>= 1) wb = fmaxf(wb, __shfl_xor_sync(0xffffffffu, wb, off));
            unsigned m = __ballot_sync(0xffffffffu, best == wb);
            int owner = __ffs(m) - 1;
            if (t == owner) {
                if (bq == 0) v0 = -3.0e38f;
                else if (bq == 1) v1 = -3.0e38f;
                else if (bq == 2) v2 = -3.0e38f;
                else v3 = -3.0e38f;
            }
            float l = wb * 10.0f;
            if (it == 0) { Lmax = l; S = 1.0f; }
            else S += __expf(l - Lmax);
        }
        float lp = p * 10.0f;
        if (lp > Lmax) { S = S * __expf(Lmax - lp) + 1.0f; Lmax = lp; }
        else S += __expf(lp - Lmax);
        float lossb = Lmax + logf(S) - lp;
        if (t == 0) atomicAdd(&g_loss, lossb);
    }
}

__global__ void k_final(float* out) {
    out[0] = g_loss * (1.0f / (float)BATCHB);
}

// ---------------- launch ----------------
extern "C" void kernel_launch(void* const* d_in, const int* in_sizes, int n_in,
                              void* d_out, int out_size) {
    const float* raw_item_embs = (const float*)d_in[0];
    const float* user_sem_base = (const float*)d_in[1];
    const float* sem_w         = (const float*)d_in[2];
    const float* sem_b         = (const float*)d_in[3];
    const float* collab_user_w = (const float*)d_in[4];
    const float* collab_item_w = (const float*)d_in[5];
    const float* adj_vals      = (const float*)d_in[6];
    const int*   adj_rows      = (const int*)d_in[7];
    const int*   adj_cols      = (const int*)d_in[8];
    const int*   uids          = (const int*)d_in[9];
    const int*   pos_iids      = (const int*)d_in[10];
    const int*   cand_ids      = (const int*)d_in[11];
    float* out = (float*)d_out;

    cudaFuncSetAttribute(k_sem_mma, cudaFuncAttributeMaxDynamicSharedMemorySize, SM_BYTES);

    cudaStream_t s2;
    cudaStreamCreateWithFlags(&s2, cudaStreamNonBlocking);
    cudaEvent_t evFork, evMark, evConv, evJoin;
    cudaEventCreateWithFlags(&evFork, cudaEventDisableTiming);
    cudaEventCreateWithFlags(&evMark, cudaEventDisableTiming);
    cudaEventCreateWithFlags(&evConv, cudaEventDisableTiming);
    cudaEventCreateWithFlags(&evJoin, cudaEventDisableTiming);

    cudaEventRecord(evFork, 0);
    cudaStreamWaitEvent(s2, evFork, 0);

    // launches 1-4 (4th = k_hist -> ncu profile lands there)
    k_zu<<<(UMARK_WORDS + 255) / 256, 256, 0, s2>>>();
    k_mark<<<(BATCHB + 255) / 256, 256, 0, s2>>>(uids);
    cudaEventRecord(evMark, s2);
    k_zero<<<(N_TOT + 255) / 256, 256>>>();
    k_hist<<<NE / 256, 256>>>(adj_rows);

    // side stream: conversion + weight split + unified sem GEMM
    k_conv<<<(N_TOT * 32 + 255) / 256, 256, 0, s2>>>(collab_user_w, collab_item_w);
    cudaEventRecord(evConv, s2);
    k_wsplit<<<(IN_DIM * BR + 255) / 256, 256, 0, s2>>>(sem_w);
    k_sem_mma<<<(M_GEMM + 127) / 128, 256, SM_BYTES, s2>>>(raw_item_embs, user_sem_base,
                                                           sem_b, uids);
    cudaEventRecord(evJoin, s2);

    // main chain: CSR build + GCN
    k_scan1<<<NB_SCAN, 256>>>();
    k_scan2<<<1, 256>>>();
    k_scan3<<<NB_SCAN, 256>>>();
    k_scatter<<<NE / 256, 256>>>(adj_rows, adj_cols, adj_vals);

    int spmm_blocks = (N_TOT * 16 + 127) / 128;
    cudaStreamWaitEvent(0, evConv, 0);
    k_spmm<0><<<spmm_blocks, 128>>>(collab_user_w, collab_item_w);
    k_spmm<1><<<spmm_blocks, 128>>>(collab_user_w, collab_item_w);
    cudaStreamWaitEvent(0, evMark, 0);
    k_spmm<2><<<spmm_blocks, 128>>>(collab_user_w, collab_item_w);

    k_collab_users<<<(BATCHB * 32 + 255) / 256, 256>>>(uids);

    cudaStreamWaitEvent(0, evJoin, 0);
    k_score<<<BATCHB, 128>>>(pos_iids, cand_ids);
    k_final<<<1, 1>>>(out);

    cudaEventDestroy(evFork);
    cudaEventDestroy(evMark);
    cudaEventDestroy(evConv);
    cudaEventDestroy(evJoin);
    cudaStreamDestroy(s2);
}